// round 1
// baseline (speedup 1.0000x reference)
#include <cuda_runtime.h>
#include <cuda_bf16.h>
#include <cstdint>
#include <cstddef>

// ---------------- constants ----------------
#define BB 1024
#define XDIM 62
#define TWIN 10
#define INCH 128
#define MIDD 256
#define OUTD 512
#define KTOT 7936          // 62*128
#define LIN1 512
#define LIN2 256

// region permutation (concatenation of REGIONS index lists; partitions 0..61)
__constant__ int c_perm[62] = {
    0,1,2,3,4,
    5,6,7,14,15,16,
    8,9,10,17,18,19,
    11,12,13,20,21,22,
    23,24,25,32,33,34,
    26,27,28,35,36,37,
    29,30,31,38,39,40,
    41,42,43,50,51,57,
    44,45,46,52,53,54,58,59,60,
    47,48,49,55,56,61};
__constant__ int c_koff[10] = {0,640,1408,2176,2944,3712,4480,5248,6016,7168};
__constant__ int c_L[10]    = {5,6,6,6,6,6,6,6,9,6};

// ---------------- scratch (device globals; no allocation allowed) ----------------
__device__ float d_gcat[BB*XDIM*384];      // [g | Ag | A2g]
__device__ float d_g1[BB*XDIM*512];
__device__ float d_regbuf[BB*KTOT];
__device__ float d_wT[KTOT*256];
__device__ float d_g2cat[BB*10*768];       // [g2in | A1 g2in | A1^2 g2in]
__device__ float d_g2[BB*10*512];
__device__ float d_outb[BB*72*512];
__device__ float d_part[32*BB*512];
__device__ float d_h1[BB*512];
__device__ float d_h2[BB*256];
__device__ float d_A2[62*62];
__device__ float d_A1s[100];
__device__ float d_mean1[512], d_rstd1[512];
__device__ float d_mean2[256], d_rstd2[256];

// ---------------- small prep kernels ----------------
__global__ void a2_k(const float* __restrict__ A, float* __restrict__ A2) {
    int i = blockIdx.x * blockDim.x + threadIdx.x;
    if (i >= 62*62) return;
    int r = i / 62, c = i % 62;
    float s = 0.f;
    for (int m = 0; m < 62; m++) s += A[r*62+m] * A[m*62+c];
    A2[i] = s;
}

__global__ void a1sq_k(const float* __restrict__ A1, float* __restrict__ A1s) {
    int i = threadIdx.x;
    if (i >= 100) return;
    int r = i / 10, c = i % 10;
    float s = 0.f;
    for (int m = 0; m < 10; m++) s += A1[r*10+m] * A1[m*10+c];
    A1s[i] = s;
}

struct RWPtrs { const float* p[10]; };

// transpose region weights rw_i[m,c,l] -> wT[(koff_i + l*128 + c)*256 + m]
__global__ void wt_k(RWPtrs rw, float* __restrict__ wT) {
    int e = blockIdx.x * 256 + threadIdx.x;   // < 7936*256
    int m = e & 255;
    int kidx = e >> 8;
    int i = 0;
#pragma unroll
    for (int q = 1; q < 10; q++) if (kidx >= c_koff[q]) i = q;
    int d = kidx - c_koff[i];
    int l = d >> 7, c = d & 127;
    wT[(size_t)kidx * 256 + m] = rw.p[i][(m * 128 + c) * c_L[i] + l];
}

// fused: variance(ddof=1) over TWIN + tfe einsum + exp gate -> g (slice 0 of gcat)
__global__ void tfe_k(const float* __restrict__ x, const float* __restrict__ w,
                      const float* __restrict__ bvec, float* __restrict__ gcat) {
    int bc = blockIdx.x;           // b*62 + c
    int c = bc % 62;
    int t = threadIdx.x;           // 0..127
    const float* xp = x + (size_t)bc * TWIN * INCH + t;
    float s1 = 0.f, s2 = 0.f, ws = 0.f;
#pragma unroll
    for (int i = 0; i < TWIN; i++) {
        float v = xp[(size_t)i * INCH];
        s1 += v; s2 += v * v;
        ws += v * w[c * TWIN + i];
    }
    float var = (s2 - s1 * s1 * 0.1f) * (1.f / 9.f);   // ddof=1
    float g = (ws + bvec[c]) * expf(-var);
    gcat[(size_t)bc * 384 + t] = g;
}

// compute Ag, A^2 g into slices 1,2 of gcat
__global__ void applyA_k(const float* __restrict__ A, const float* __restrict__ A2,
                         float* __restrict__ gcat) {
    __shared__ float gs[62][128];
    int b = blockIdx.x;
    int t = threadIdx.x;   // 128
    int yy = threadIdx.y;  // 4
    for (int n = yy; n < 62; n += 4)
        gs[n][t] = gcat[((size_t)b * 62 + n) * 384 + t];
    __syncthreads();
    for (int n = yy; n < 62; n += 4) {
        float s1 = 0.f, s2 = 0.f;
#pragma unroll 2
        for (int m = 0; m < 62; m++) {
            float v = gs[m][t];
            s1 += A[n * 62 + m] * v;
            s2 += A2[n * 62 + m] * v;
        }
        gcat[((size_t)b * 62 + n) * 384 + 128 + t] = s1;
        gcat[((size_t)b * 62 + n) * 384 + 256 + t] = s2;
    }
}

// gather permuted region rows: regbuf[b, j] = g[b, perm[j/128], j%128]
__global__ void gather_k(const float* __restrict__ gcat, float* __restrict__ regbuf) {
    size_t e = (size_t)blockIdx.x * 256 + threadIdx.x;   // < 1024*7936
    int b = (int)(e / KTOT);
    int j = (int)(e % KTOT);
    int l = j >> 7, c = j & 127;
    regbuf[e] = gcat[((size_t)b * 62 + c_perm[l]) * 384 + c];
}

// A1, A1^2 apply for cheby2 (slices 1,2 of g2cat)
__global__ void applyA1_k(const float* __restrict__ A1, const float* __restrict__ A1s,
                          float* __restrict__ g2cat) {
    int b = blockIdx.x;
    int t = threadIdx.x;   // 256
    float v[10];
#pragma unroll
    for (int m = 0; m < 10; m++) v[m] = g2cat[((size_t)b * 10 + m) * 768 + t];
#pragma unroll
    for (int n = 0; n < 10; n++) {
        float s1 = 0.f, s2 = 0.f;
#pragma unroll
        for (int m = 0; m < 10; m++) {
            s1 += A1[n * 10 + m] * v[m];
            s2 += A1s[n * 10 + m] * v[m];
        }
        g2cat[((size_t)b * 10 + n) * 768 + 256 + t] = s1;
        g2cat[((size_t)b * 10 + n) * 768 + 512 + t] = s2;
    }
}

// ---------------- generic tiled SGEMM (64x64x16, 256 thr, 4x4 micro) ----------------
// requires M%64==0, N%64==0, K%16==0 (true for every call here)
template<bool RELU, bool BIAS, bool SPLIT>
__global__ void sgemm_k(const float* __restrict__ A, const float* __restrict__ Bm,
                        float* __restrict__ C, const float* __restrict__ bias,
                        int M, int N, int K, int lda, int ldb, int ldc) {
    __shared__ float As[16][68];   // transposed A tile, padded
    __shared__ float Bs[16][64];
    int tid = threadIdx.x;
    int tx = tid & 15, ty = tid >> 4;
    int row0 = blockIdx.x * 64, col0 = blockIdx.y * 64;
    if (SPLIT) {
        A  += (size_t)blockIdx.z * K;               // advance along k
        Bm += (size_t)blockIdx.z * K * ldb;
        C  += (size_t)blockIdx.z * (size_t)M * N;   // partials
    }
    float acc[4][4] = {};
    int ar = tid >> 2;            // 0..63 row within A tile
    int ac = (tid & 3) * 4;       // 0,4,8,12 k within tile
    int br = tid >> 6;            // 0..3
    int bc = tid & 63;
    for (int k0 = 0; k0 < K; k0 += 16) {
        float4 av = *(const float4*)&A[(size_t)(row0 + ar) * lda + k0 + ac];
        As[ac + 0][ar] = av.x;
        As[ac + 1][ar] = av.y;
        As[ac + 2][ar] = av.z;
        As[ac + 3][ar] = av.w;
#pragma unroll
        for (int i = 0; i < 4; i++)
            Bs[br + i * 4][bc] = Bm[(size_t)(k0 + br + i * 4) * ldb + col0 + bc];
        __syncthreads();
#pragma unroll
        for (int kk = 0; kk < 16; kk++) {
            float4 a4 = *(const float4*)&As[kk][ty * 4];
            float4 b4 = *(const float4*)&Bs[kk][tx * 4];
            float a[4] = {a4.x, a4.y, a4.z, a4.w};
            float bv[4] = {b4.x, b4.y, b4.z, b4.w};
#pragma unroll
            for (int i = 0; i < 4; i++)
#pragma unroll
                for (int j = 0; j < 4; j++)
                    acc[i][j] += a[i] * bv[j];
        }
        __syncthreads();
    }
#pragma unroll
    for (int i = 0; i < 4; i++) {
        int r = row0 + ty * 4 + i;
#pragma unroll
        for (int j = 0; j < 4; j++) {
            int c = col0 + tx * 4 + j;
            float v = acc[i][j];
            if (BIAS) v += bias[c];
            if (RELU) v = fmaxf(v, 0.f);
            C[(size_t)r * ldc + c] = v;
        }
    }
}

// ---------------- softmax gate ----------------
__global__ void softgate_k(const float* __restrict__ g1, const float* __restrict__ g2,
                           const float* __restrict__ bg, const float* __restrict__ cg,
                           float* __restrict__ outb) {
    int b = blockIdx.x;
    int o = threadIdx.x;   // 512
    float Bg = *bg, Cg = *cg;
    float M = -1e30f, S = 0.f;
    for (int s = 0; s < 72; s++) {
        float v = (s < 62) ? g1[((size_t)b * 62 + s) * 512 + o]
                           : g2[((size_t)b * 10 + (s - 62)) * 512 + o];
        float a = ((s < 62) ? Bg : Cg) * v;
        float nM = fmaxf(M, a);
        S = S * expf(M - nM) + expf(a - nM);
        M = nM;
    }
    float inv = 1.f / S;
    for (int s = 0; s < 72; s++) {
        float v = (s < 62) ? g1[((size_t)b * 62 + s) * 512 + o]
                           : g2[((size_t)b * 10 + (s - 62)) * 512 + o];
        float a = ((s < 62) ? Bg : Cg) * v;
        outb[(size_t)b * 36864 + s * 512 + o] = expf(a - M) * inv * v;
    }
}

// ---------------- split-K reduce (bias cancels in BN; skipped) ----------------
__global__ void reduce_part_k(const float* __restrict__ part, float* __restrict__ out) {
    int i = blockIdx.x * 256 + threadIdx.x;   // < 1024*512
    float s = 0.f;
#pragma unroll
    for (int z = 0; z < 32; z++) s += part[(size_t)z * (BB * 512) + i];
    out[i] = s;
}

// ---------------- batch-norm stats + bn*gelu ----------------
__global__ void bnstats_k(const float* __restrict__ h, int F,
                          float* __restrict__ mean, float* __restrict__ rstd) {
    __shared__ float sh1[256], sh2[256];
    int j = blockIdx.x;
    float s1 = 0.f, s2 = 0.f;
    for (int b = threadIdx.x; b < BB; b += 256) {
        float v = h[(size_t)b * F + j];
        s1 += v; s2 += v * v;
    }
    sh1[threadIdx.x] = s1; sh2[threadIdx.x] = s2;
    __syncthreads();
    for (int o = 128; o; o >>= 1) {
        if (threadIdx.x < o) {
            sh1[threadIdx.x] += sh1[threadIdx.x + o];
            sh2[threadIdx.x] += sh2[threadIdx.x + o];
        }
        __syncthreads();
    }
    if (threadIdx.x == 0) {
        float mu = sh1[0] * (1.f / BB);
        float var = sh2[0] * (1.f / BB) - mu * mu;
        mean[j] = mu;
        rstd[j] = rsqrtf(var + 1e-5f);
    }
}

__global__ void bngelu_k(float* __restrict__ h, int F,
                         const float* __restrict__ mean, const float* __restrict__ rstd,
                         const float* __restrict__ gam, const float* __restrict__ bet) {
    int i = blockIdx.x * 256 + threadIdx.x;
    int j = i % F;
    float v = (h[i] - mean[j]) * rstd[j] * gam[j] + bet[j];
    h[i] = 0.5f * v * (1.f + erff(v * 0.70710678118654752f));
}

// ---------------- final linear + softmax ----------------
__global__ void final_k(const float* __restrict__ h2, const float* __restrict__ w3,
                        const float* __restrict__ b3, float* __restrict__ out) {
    int b = blockIdx.x;
    int lane = threadIdx.x;   // 32
    float acc[4] = {0.f, 0.f, 0.f, 0.f};
    for (int k = lane; k < 256; k += 32) {
        float v = h2[(size_t)b * 256 + k];
#pragma unroll
        for (int j = 0; j < 4; j++) acc[j] += v * w3[k * 4 + j];
    }
#pragma unroll
    for (int off = 16; off; off >>= 1)
#pragma unroll
        for (int j = 0; j < 4; j++)
            acc[j] += __shfl_down_sync(0xffffffffu, acc[j], off);
    if (lane == 0) {
        float l[4];
#pragma unroll
        for (int j = 0; j < 4; j++) l[j] = acc[j] + b3[j];
        float m = fmaxf(fmaxf(l[0], l[1]), fmaxf(l[2], l[3]));
        float e[4], s = 0.f;
#pragma unroll
        for (int j = 0; j < 4; j++) { e[j] = expf(l[j] - m); s += e[j]; }
        float inv = 1.f / s;
#pragma unroll
        for (int j = 0; j < 4; j++) out[b * 4 + j] = e[j] * inv;
    }
}

// ---------------- host ----------------
static float* sym(const void* s) {
    void* p = nullptr;
    cudaGetSymbolAddress(&p, s);
    return (float*)p;
}

extern "C" void kernel_launch(void* const* d_in, const int* in_sizes, int n_in,
                              void* d_out, int out_size) {
    const float* x        = (const float*)d_in[0];
    const float* tfe_w    = (const float*)d_in[1];
    const float* tfe_b    = (const float*)d_in[2];
    const float* cheby1_w = (const float*)d_in[3];
    const float* A        = (const float*)d_in[4];
    const float* cheby2_w = (const float*)d_in[5];
    const float* A1       = (const float*)d_in[6];
    const float* b_gate   = (const float*)d_in[7];
    const float* c_gate   = (const float*)d_in[8];

    const float *rw[10], *region_b, *hc_w1, *bn1_g, *bn1_b;
    const float *hc_w2, *bn2_g, *bn2_b, *hc_w3, *hc_b3;

    if (in_sizes[9] == 2560) {
        // dict insertion order: region_b..hc_b3 then rw1..rw10
        region_b = (const float*)d_in[9];
        hc_w1    = (const float*)d_in[10];
        bn1_g    = (const float*)d_in[12];
        bn1_b    = (const float*)d_in[13];
        hc_w2    = (const float*)d_in[14];
        bn2_g    = (const float*)d_in[16];
        bn2_b    = (const float*)d_in[17];
        hc_w3    = (const float*)d_in[18];
        hc_b3    = (const float*)d_in[19];
        for (int i = 0; i < 10; i++) rw[i] = (const float*)d_in[20 + i];
    } else {
        // reference signature order: rw1..rw10 then region_b..hc_b3
        for (int i = 0; i < 10; i++) rw[i] = (const float*)d_in[9 + i];
        region_b = (const float*)d_in[19];
        hc_w1    = (const float*)d_in[20];
        bn1_g    = (const float*)d_in[22];
        bn1_b    = (const float*)d_in[23];
        hc_w2    = (const float*)d_in[24];
        bn2_g    = (const float*)d_in[26];
        bn2_b    = (const float*)d_in[27];
        hc_w3    = (const float*)d_in[28];
        hc_b3    = (const float*)d_in[29];
    }

    float* p_gcat   = sym(d_gcat);
    float* p_g1     = sym(d_g1);
    float* p_regbuf = sym(d_regbuf);
    float* p_wT     = sym(d_wT);
    float* p_g2cat  = sym(d_g2cat);
    float* p_g2     = sym(d_g2);
    float* p_outb   = sym(d_outb);
    float* p_part   = sym(d_part);
    float* p_h1     = sym(d_h1);
    float* p_h2     = sym(d_h2);
    float* p_A2     = sym(d_A2);
    float* p_A1s    = sym(d_A1s);
    float* p_mean1  = sym(d_mean1);
    float* p_rstd1  = sym(d_rstd1);
    float* p_mean2  = sym(d_mean2);
    float* p_rstd2  = sym(d_rstd2);

    // prep
    a2_k<<<16, 256>>>(A, p_A2);
    a1sq_k<<<1, 128>>>(A1, p_A1s);
    RWPtrs rwp;
    for (int i = 0; i < 10; i++) rwp.p[i] = rw[i];
    wt_k<<<KTOT, 256>>>(rwp, p_wT);

    // front-end fuse
    tfe_k<<<BB * XDIM, 128>>>(x, tfe_w, tfe_b, p_gcat);
    applyA_k<<<BB, dim3(128, 4)>>>(A, p_A2, p_gcat);

    // cheby1: (63488 x 384) @ (384 x 512) + relu
    sgemm_k<true, false, false><<<dim3(992, 8), 256>>>(
        p_gcat, cheby1_w, p_g1, nullptr, 63488, 512, 384, 384, 512, 512);

    // regions
    gather_k<<<BB * KTOT / 256, 256>>>(p_gcat, p_regbuf);
    const int koff[10] = {0,640,1408,2176,2944,3712,4480,5248,6016,7168};
    const int Lr[10]   = {5,6,6,6,6,6,6,6,9,6};
    for (int i = 0; i < 10; i++) {
        sgemm_k<false, true, false><<<dim3(16, 4), 256>>>(
            p_regbuf + koff[i], p_wT + (size_t)koff[i] * 256,
            p_g2cat + i * 768, region_b + i * 256,
            1024, 256, Lr[i] * 128, KTOT, 256, 7680);
    }

    // cheby2
    applyA1_k<<<BB, 256>>>(A1, p_A1s, p_g2cat);
    sgemm_k<true, false, false><<<dim3(160, 8), 256>>>(
        p_g2cat, cheby2_w, p_g2, nullptr, 10240, 512, 768, 768, 512, 512);

    // softmax gate -> (B, 36864)
    softgate_k<<<BB, 512>>>(p_g1, p_g2, b_gate, c_gate, p_outb);

    // hc_w1: (1024 x 36864) @ (36864 x 512), split-K=32 (hc_b1 cancels in BN)
    sgemm_k<false, false, true><<<dim3(16, 8, 32), 256>>>(
        p_outb, hc_w1, p_part, nullptr, 1024, 512, 1152, 36864, 512, 512);
    reduce_part_k<<<2048, 256>>>(p_part, p_h1);

    bnstats_k<<<512, 256>>>(p_h1, 512, p_mean1, p_rstd1);
    bngelu_k<<<2048, 256>>>(p_h1, 512, p_mean1, p_rstd1, bn1_g, bn1_b);

    // hc_w2 (hc_b2 cancels in BN)
    sgemm_k<false, false, false><<<dim3(16, 4), 256>>>(
        p_h1, hc_w2, p_h2, nullptr, 1024, 256, 512, 512, 256, 256);
    bnstats_k<<<256, 256>>>(p_h2, 256, p_mean2, p_rstd2);
    bngelu_k<<<1024, 256>>>(p_h2, 256, p_mean2, p_rstd2, bn2_g, bn2_b);

    // final linear + softmax
    final_k<<<BB, 32>>>(p_h2, hc_w3, hc_b3, (float*)d_out);
}

// round 2
// speedup vs baseline: 3.3156x; 3.3156x over previous
#include <cuda_runtime.h>
#include <cuda_bf16.h>
#include <cstdint>
#include <cstddef>

// ---------------- constants ----------------
#define BB 1024
#define XDIM 62
#define TWIN 10
#define INCH 128
#define MIDD 256
#define OUTD 512
#define KTOT 7936          // 62*128
#define SPLITZ 16

// region permutation (concatenation of REGIONS index lists; partitions 0..61)
__constant__ int c_perm[62] = {
    0,1,2,3,4,
    5,6,7,14,15,16,
    8,9,10,17,18,19,
    11,12,13,20,21,22,
    23,24,25,32,33,34,
    26,27,28,35,36,37,
    29,30,31,38,39,40,
    41,42,43,50,51,57,
    44,45,46,52,53,54,58,59,60,
    47,48,49,55,56,61};
__constant__ int c_koff[10] = {0,640,1408,2176,2944,3712,4480,5248,6016,7168};
__constant__ int c_L[10]    = {5,6,6,6,6,6,6,6,9,6};

// ---------------- scratch (device globals; no allocation allowed) ----------------
__device__ float d_gcat[BB*XDIM*384];      // [g | Ag | A2g]
__device__ float d_g1[BB*XDIM*512];
__device__ float d_regbuf[BB*KTOT];
__device__ float d_wT[KTOT*256];
__device__ float d_g2cat[BB*10*768];       // [g2in | A1 g2in | A1^2 g2in]
__device__ float d_g2[BB*10*512];
__device__ float d_outb[BB*72*512];
__device__ float d_part[SPLITZ*BB*512];
__device__ float d_h1[BB*512];
__device__ float d_h2[BB*256];
__device__ float d_A2[62*62];
__device__ float d_A1s[100];
__device__ float d_mean1[512], d_rstd1[512];
__device__ float d_mean2[256], d_rstd2[256];

// ---------------- tf32 helpers ----------------
__device__ __forceinline__ uint32_t f2tf(float f) {
    uint32_t u;
    asm("cvt.rna.tf32.f32 %0, %1;" : "=r"(u) : "f"(f));
    return u;
}

__device__ __forceinline__ void mma8(float* d, const uint32_t* a, uint32_t b0, uint32_t b1) {
    asm volatile(
        "mma.sync.aligned.m16n8k8.row.col.f32.tf32.tf32.f32 "
        "{%0,%1,%2,%3},{%4,%5,%6,%7},{%8,%9},{%0,%1,%2,%3};\n"
        : "+f"(d[0]), "+f"(d[1]), "+f"(d[2]), "+f"(d[3])
        : "r"(a[0]), "r"(a[1]), "r"(a[2]), "r"(a[3]), "r"(b0), "r"(b1));
}

// ---------------- tf32 tensor-core GEMM ----------------
// CTA tile 128x128, K-step 16, 256 threads = 8 warps (4M x 2N), warp tile 32x64.
// grid: x = col tiles, y = row tiles, z = split-K chunk or region index.
// Requires M%128==0, N%128==0, K%16==0 (true for every call here).
template<bool RELU, bool BIAS, bool SPLITK, bool REGION>
__global__ __launch_bounds__(256, 2)
void tf32gemm_k(const float* __restrict__ A, const float* __restrict__ Bm,
                float* __restrict__ C, const float* __restrict__ bias,
                int M, int N, int K, int lda, int ldb, int ldc) {
    __shared__ uint32_t As[128][20];   // padded: conflict-free frag loads
    __shared__ uint32_t Bs[16][136];

    int tid = threadIdx.x;

    if (REGION) {
        int rz = blockIdx.z;
        A    += c_koff[rz];
        Bm   += (size_t)c_koff[rz] * ldb;
        C    += rz * 768;
        if (BIAS) bias += rz * MIDD;
        K = c_L[rz] * 128;
    }
    if (SPLITK) {
        A  += (size_t)blockIdx.z * K;
        Bm += (size_t)blockIdx.z * K * ldb;
        C  += (size_t)blockIdx.z * (size_t)M * N;
    }

    int row0 = blockIdx.y * 128, col0 = blockIdx.x * 128;

    // gmem staging indices
    int ar = tid >> 1, aseg = (tid & 1) * 8;     // A: 128 rows x 16 k
    int br = tid >> 4, bc = (tid & 15) * 8;      // B: 16 k x 128 n
    const float* Ap = A + (size_t)(row0 + ar) * lda + aseg;
    const float* Bp = Bm + (size_t)br * ldb + col0 + bc;

    int lane = tid & 31, wid = tid >> 5;
    int wm = wid >> 1, wn = wid & 1;
    int g = lane >> 2, t = lane & 3;

    float acc[2][8][4] = {};

    // prefetch first tile
    float4 av0 = *(const float4*)(Ap);
    float4 av1 = *(const float4*)(Ap + 4);
    float4 bv0 = *(const float4*)(Bp);
    float4 bv1 = *(const float4*)(Bp + 4);

    for (int k0 = 0; k0 < K; k0 += 16) {
        // stage (converted to tf32) into smem
        As[ar][aseg + 0] = f2tf(av0.x); As[ar][aseg + 1] = f2tf(av0.y);
        As[ar][aseg + 2] = f2tf(av0.z); As[ar][aseg + 3] = f2tf(av0.w);
        As[ar][aseg + 4] = f2tf(av1.x); As[ar][aseg + 5] = f2tf(av1.y);
        As[ar][aseg + 6] = f2tf(av1.z); As[ar][aseg + 7] = f2tf(av1.w);
        Bs[br][bc + 0] = f2tf(bv0.x); Bs[br][bc + 1] = f2tf(bv0.y);
        Bs[br][bc + 2] = f2tf(bv0.z); Bs[br][bc + 3] = f2tf(bv0.w);
        Bs[br][bc + 4] = f2tf(bv1.x); Bs[br][bc + 5] = f2tf(bv1.y);
        Bs[br][bc + 6] = f2tf(bv1.z); Bs[br][bc + 7] = f2tf(bv1.w);
        __syncthreads();

        // prefetch next tile while computing
        if (k0 + 16 < K) {
            av0 = *(const float4*)(Ap + k0 + 16);
            av1 = *(const float4*)(Ap + k0 + 20);
            bv0 = *(const float4*)(Bp + (size_t)(k0 + 16) * ldb);
            bv1 = *(const float4*)(Bp + (size_t)(k0 + 16) * ldb + 4);
        }

#pragma unroll
        for (int kt = 0; kt < 16; kt += 8) {
            uint32_t a[2][4];
#pragma unroll
            for (int mm = 0; mm < 2; mm++) {
                int r = wm * 32 + mm * 16 + g;
                a[mm][0] = As[r][kt + t];
                a[mm][1] = As[r + 8][kt + t];
                a[mm][2] = As[r][kt + t + 4];
                a[mm][3] = As[r + 8][kt + t + 4];
            }
#pragma unroll
            for (int nn = 0; nn < 8; nn++) {
                int cb = wn * 64 + nn * 8 + g;
                uint32_t b0 = Bs[kt + t][cb];
                uint32_t b1 = Bs[kt + t + 4][cb];
                mma8(acc[0][nn], a[0], b0, b1);
                mma8(acc[1][nn], a[1], b0, b1);
            }
        }
        __syncthreads();
    }

    // epilogue
#pragma unroll
    for (int mm = 0; mm < 2; mm++) {
        int r = row0 + wm * 32 + mm * 16 + g;
#pragma unroll
        for (int nn = 0; nn < 8; nn++) {
            int c = col0 + wn * 64 + nn * 8 + 2 * t;
            float v0 = acc[mm][nn][0], v1 = acc[mm][nn][1];
            float v2 = acc[mm][nn][2], v3 = acc[mm][nn][3];
            if (BIAS) {
                float q0 = bias[c], q1 = bias[c + 1];
                v0 += q0; v1 += q1; v2 += q0; v3 += q1;
            }
            if (RELU) {
                v0 = fmaxf(v0, 0.f); v1 = fmaxf(v1, 0.f);
                v2 = fmaxf(v2, 0.f); v3 = fmaxf(v3, 0.f);
            }
            *(float2*)&C[(size_t)r * ldc + c] = make_float2(v0, v1);
            *(float2*)&C[(size_t)(r + 8) * ldc + c] = make_float2(v2, v3);
        }
    }
}

// ---------------- small prep kernels ----------------
__global__ void a2_k(const float* __restrict__ A, float* __restrict__ A2) {
    int i = blockIdx.x * blockDim.x + threadIdx.x;
    if (i >= 62*62) return;
    int r = i / 62, c = i % 62;
    float s = 0.f;
    for (int m = 0; m < 62; m++) s += A[r*62+m] * A[m*62+c];
    A2[i] = s;
}

__global__ void a1sq_k(const float* __restrict__ A1, float* __restrict__ A1s) {
    int i = threadIdx.x;
    if (i >= 100) return;
    int r = i / 10, c = i % 10;
    float s = 0.f;
    for (int m = 0; m < 10; m++) s += A1[r*10+m] * A1[m*10+c];
    A1s[i] = s;
}

struct RWPtrs { const float* p[10]; };

// transpose region weights rw_i[m,c,l] -> wT[(koff_i + l*128 + c)*256 + m]
__global__ void wt_k(RWPtrs rw, float* __restrict__ wT) {
    int e = blockIdx.x * 256 + threadIdx.x;   // < 7936*256
    int m = e & 255;
    int kidx = e >> 8;
    int i = 0;
#pragma unroll
    for (int q = 1; q < 10; q++) if (kidx >= c_koff[q]) i = q;
    int d = kidx - c_koff[i];
    int l = d >> 7, c = d & 127;
    wT[(size_t)kidx * 256 + m] = rw.p[i][(m * 128 + c) * c_L[i] + l];
}

// fused: variance(ddof=1) over TWIN + tfe einsum + exp gate -> g (slice 0 of gcat)
__global__ void tfe_k(const float* __restrict__ x, const float* __restrict__ w,
                      const float* __restrict__ bvec, float* __restrict__ gcat) {
    int bc = blockIdx.x;           // b*62 + c
    int c = bc % 62;
    int t = threadIdx.x;           // 0..127
    const float* xp = x + (size_t)bc * TWIN * INCH + t;
    float s1 = 0.f, s2 = 0.f, ws = 0.f;
#pragma unroll
    for (int i = 0; i < TWIN; i++) {
        float v = xp[(size_t)i * INCH];
        s1 += v; s2 += v * v;
        ws += v * w[c * TWIN + i];
    }
    float var = (s2 - s1 * s1 * 0.1f) * (1.f / 9.f);   // ddof=1
    float g = (ws + bvec[c]) * expf(-var);
    gcat[(size_t)bc * 384 + t] = g;
}

// compute Ag, A^2 g into slices 1,2 of gcat (register-blocked 4 rows)
__global__ void applyA_k(const float* __restrict__ A, const float* __restrict__ A2,
                         float* __restrict__ gcat) {
    __shared__ float gs[62][128];
    int b = blockIdx.x;
    int t = threadIdx.x;   // 128
    int yy = threadIdx.y;  // 4
    for (int n = yy; n < 62; n += 4)
        gs[n][t] = gcat[((size_t)b * 62 + n) * 384 + t];
    __syncthreads();
    // each y-thread handles rows yy, yy+16, yy+32, yy+48 (62 rows: last group partial)
#pragma unroll
    for (int base = 0; base < 64; base += 16) {
        int n = base + yy * 4;   // process 4 consecutive rows n..n+3 when valid
        float s1[4] = {0,0,0,0}, s2[4] = {0,0,0,0};
        bool val[4];
#pragma unroll
        for (int q = 0; q < 4; q++) val[q] = (n + q) < 62;
        for (int m = 0; m < 62; m++) {
            float v = gs[m][t];
#pragma unroll
            for (int q = 0; q < 4; q++) {
                if (val[q]) {
                    s1[q] += A[(n + q) * 62 + m] * v;
                    s2[q] += A2[(n + q) * 62 + m] * v;
                }
            }
        }
#pragma unroll
        for (int q = 0; q < 4; q++) {
            if (val[q]) {
                gcat[((size_t)b * 62 + n + q) * 384 + 128 + t] = s1[q];
                gcat[((size_t)b * 62 + n + q) * 384 + 256 + t] = s2[q];
            }
        }
    }
}

// gather permuted region rows: regbuf[b, j] = g[b, perm[j/128], j%128]
__global__ void gather_k(const float* __restrict__ gcat, float* __restrict__ regbuf) {
    size_t e = (size_t)blockIdx.x * 256 + threadIdx.x;   // < 1024*7936
    int b = (int)(e / KTOT);
    int j = (int)(e % KTOT);
    int l = j >> 7, c = j & 127;
    regbuf[e] = gcat[((size_t)b * 62 + c_perm[l]) * 384 + c];
}

// A1, A1^2 apply for cheby2 (slices 1,2 of g2cat)
__global__ void applyA1_k(const float* __restrict__ A1, const float* __restrict__ A1s,
                          float* __restrict__ g2cat) {
    int b = blockIdx.x;
    int t = threadIdx.x;   // 256
    float v[10];
#pragma unroll
    for (int m = 0; m < 10; m++) v[m] = g2cat[((size_t)b * 10 + m) * 768 + t];
#pragma unroll
    for (int n = 0; n < 10; n++) {
        float s1 = 0.f, s2 = 0.f;
#pragma unroll
        for (int m = 0; m < 10; m++) {
            s1 += A1[n * 10 + m] * v[m];
            s2 += A1s[n * 10 + m] * v[m];
        }
        g2cat[((size_t)b * 10 + n) * 768 + 256 + t] = s1;
        g2cat[((size_t)b * 10 + n) * 768 + 512 + t] = s2;
    }
}

// ---------------- softmax gate (smem-staged, single global read) ----------------
__global__ void softgate_k(const float* __restrict__ g1, const float* __restrict__ g2,
                           const float* __restrict__ bg, const float* __restrict__ cg,
                           float* __restrict__ outb) {
    extern __shared__ float sm[];   // 72 * 512
    int b = blockIdx.x;
    int o = threadIdx.x;   // 512
    float Bg = *bg, Cg = *cg;
#pragma unroll 2
    for (int s = 0; s < 62; s++)
        sm[s * 512 + o] = g1[((size_t)b * 62 + s) * 512 + o];
#pragma unroll
    for (int s = 0; s < 10; s++)
        sm[(62 + s) * 512 + o] = g2[((size_t)b * 10 + s) * 512 + o];
    __syncthreads();
    float M = -1e30f, S = 0.f;
#pragma unroll 2
    for (int s = 0; s < 72; s++) {
        float a = ((s < 62) ? Bg : Cg) * sm[s * 512 + o];
        float nM = fmaxf(M, a);
        S = S * expf(M - nM) + expf(a - nM);
        M = nM;
    }
    float inv = 1.f / S;
#pragma unroll 2
    for (int s = 0; s < 72; s++) {
        float v = sm[s * 512 + o];
        float a = ((s < 62) ? Bg : Cg) * v;
        outb[(size_t)b * 36864 + s * 512 + o] = expf(a - M) * inv * v;
    }
}

// ---------------- split-K reduce (bias cancels in BN; skipped) ----------------
__global__ void reduce_part_k(const float* __restrict__ part, float* __restrict__ out) {
    int i = blockIdx.x * 256 + threadIdx.x;   // < 1024*512
    float s = 0.f;
#pragma unroll
    for (int z = 0; z < SPLITZ; z++) s += part[(size_t)z * (BB * 512) + i];
    out[i] = s;
}

// ---------------- batch-norm stats + bn*gelu ----------------
__global__ void bnstats_k(const float* __restrict__ h, int F,
                          float* __restrict__ mean, float* __restrict__ rstd) {
    __shared__ float sh1[256], sh2[256];
    int j = blockIdx.x;
    float s1 = 0.f, s2 = 0.f;
    for (int b = threadIdx.x; b < BB; b += 256) {
        float v = h[(size_t)b * F + j];
        s1 += v; s2 += v * v;
    }
    sh1[threadIdx.x] = s1; sh2[threadIdx.x] = s2;
    __syncthreads();
    for (int o = 128; o; o >>= 1) {
        if (threadIdx.x < o) {
            sh1[threadIdx.x] += sh1[threadIdx.x + o];
            sh2[threadIdx.x] += sh2[threadIdx.x + o];
        }
        __syncthreads();
    }
    if (threadIdx.x == 0) {
        float mu = sh1[0] * (1.f / BB);
        float var = sh2[0] * (1.f / BB) - mu * mu;
        mean[j] = mu;
        rstd[j] = rsqrtf(var + 1e-5f);
    }
}

__global__ void bngelu_k(float* __restrict__ h, int F,
                         const float* __restrict__ mean, const float* __restrict__ rstd,
                         const float* __restrict__ gam, const float* __restrict__ bet) {
    int i = blockIdx.x * 256 + threadIdx.x;
    int j = i % F;
    float v = (h[i] - mean[j]) * rstd[j] * gam[j] + bet[j];
    h[i] = 0.5f * v * (1.f + erff(v * 0.70710678118654752f));
}

// ---------------- final linear + softmax ----------------
__global__ void final_k(const float* __restrict__ h2, const float* __restrict__ w3,
                        const float* __restrict__ b3, float* __restrict__ out) {
    int b = blockIdx.x;
    int lane = threadIdx.x;   // 32
    float acc[4] = {0.f, 0.f, 0.f, 0.f};
    for (int k = lane; k < 256; k += 32) {
        float v = h2[(size_t)b * 256 + k];
#pragma unroll
        for (int j = 0; j < 4; j++) acc[j] += v * w3[k * 4 + j];
    }
#pragma unroll
    for (int off = 16; off; off >>= 1)
#pragma unroll
        for (int j = 0; j < 4; j++)
            acc[j] += __shfl_down_sync(0xffffffffu, acc[j], off);
    if (lane == 0) {
        float l[4];
#pragma unroll
        for (int j = 0; j < 4; j++) l[j] = acc[j] + b3[j];
        float m = fmaxf(fmaxf(l[0], l[1]), fmaxf(l[2], l[3]));
        float e[4], s = 0.f;
#pragma unroll
        for (int j = 0; j < 4; j++) { e[j] = expf(l[j] - m); s += e[j]; }
        float inv = 1.f / s;
#pragma unroll
        for (int j = 0; j < 4; j++) out[b * 4 + j] = e[j] * inv;
    }
}

// ---------------- host ----------------
static float* sym(const void* s) {
    void* p = nullptr;
    cudaGetSymbolAddress(&p, s);
    return (float*)p;
}

extern "C" void kernel_launch(void* const* d_in, const int* in_sizes, int n_in,
                              void* d_out, int out_size) {
    const float* x        = (const float*)d_in[0];
    const float* tfe_w    = (const float*)d_in[1];
    const float* tfe_b    = (const float*)d_in[2];
    const float* cheby1_w = (const float*)d_in[3];
    const float* A        = (const float*)d_in[4];
    const float* cheby2_w = (const float*)d_in[5];
    const float* A1       = (const float*)d_in[6];
    const float* b_gate   = (const float*)d_in[7];
    const float* c_gate   = (const float*)d_in[8];

    const float *rw[10], *region_b, *hc_w1, *bn1_g, *bn1_b;
    const float *hc_w2, *bn2_g, *bn2_b, *hc_w3, *hc_b3;

    if (in_sizes[9] == 2560) {
        // dict insertion order: region_b..hc_b3 then rw1..rw10
        region_b = (const float*)d_in[9];
        hc_w1    = (const float*)d_in[10];
        bn1_g    = (const float*)d_in[12];
        bn1_b    = (const float*)d_in[13];
        hc_w2    = (const float*)d_in[14];
        bn2_g    = (const float*)d_in[16];
        bn2_b    = (const float*)d_in[17];
        hc_w3    = (const float*)d_in[18];
        hc_b3    = (const float*)d_in[19];
        for (int i = 0; i < 10; i++) rw[i] = (const float*)d_in[20 + i];
    } else {
        // reference signature order: rw1..rw10 then region_b..hc_b3
        for (int i = 0; i < 10; i++) rw[i] = (const float*)d_in[9 + i];
        region_b = (const float*)d_in[19];
        hc_w1    = (const float*)d_in[20];
        bn1_g    = (const float*)d_in[22];
        bn1_b    = (const float*)d_in[23];
        hc_w2    = (const float*)d_in[24];
        bn2_g    = (const float*)d_in[26];
        bn2_b    = (const float*)d_in[27];
        hc_w3    = (const float*)d_in[28];
        hc_b3    = (const float*)d_in[29];
    }

    float* p_gcat   = sym(d_gcat);
    float* p_g1     = sym(d_g1);
    float* p_regbuf = sym(d_regbuf);
    float* p_wT     = sym(d_wT);
    float* p_g2cat  = sym(d_g2cat);
    float* p_g2     = sym(d_g2);
    float* p_outb   = sym(d_outb);
    float* p_part   = sym(d_part);
    float* p_h1     = sym(d_h1);
    float* p_h2     = sym(d_h2);
    float* p_A2     = sym(d_A2);
    float* p_A1s    = sym(d_A1s);
    float* p_mean1  = sym(d_mean1);
    float* p_rstd1  = sym(d_rstd1);
    float* p_mean2  = sym(d_mean2);
    float* p_rstd2  = sym(d_rstd2);

    static bool attr_done = false;
    if (!attr_done) {
        cudaFuncSetAttribute(softgate_k, cudaFuncAttributeMaxDynamicSharedMemorySize,
                             72 * 512 * 4);
        attr_done = true;
    }

    // prep
    a2_k<<<16, 256>>>(A, p_A2);
    a1sq_k<<<1, 128>>>(A1, p_A1s);
    RWPtrs rwp;
    for (int i = 0; i < 10; i++) rwp.p[i] = rw[i];
    wt_k<<<KTOT, 256>>>(rwp, p_wT);

    // front-end fuse
    tfe_k<<<BB * XDIM, 128>>>(x, tfe_w, tfe_b, p_gcat);
    applyA_k<<<BB, dim3(128, 4)>>>(A, p_A2, p_gcat);

    // cheby1: (63488 x 384) @ (384 x 512) + relu   [tensor core tf32]
    tf32gemm_k<true, false, false, false><<<dim3(4, 496), 256>>>(
        p_gcat, cheby1_w, p_g1, nullptr, 63488, 512, 384, 384, 512, 512);

    // regions: batched 10 GEMMs (1024 x 256, K = L_i*128) + bias
    gather_k<<<BB * KTOT / 256, 256>>>(p_gcat, p_regbuf);
    tf32gemm_k<false, true, false, true><<<dim3(2, 8, 10), 256>>>(
        p_regbuf, p_wT, p_g2cat, region_b, 1024, 256, 0, KTOT, 256, 7680);

    // cheby2
    applyA1_k<<<BB, 256>>>(A1, p_A1s, p_g2cat);
    tf32gemm_k<true, false, false, false><<<dim3(4, 80), 256>>>(
        p_g2cat, cheby2_w, p_g2, nullptr, 10240, 512, 768, 768, 512, 512);

    // softmax gate -> (B, 36864)
    softgate_k<<<BB, 512, 72 * 512 * 4>>>(p_g1, p_g2, b_gate, c_gate, p_outb);

    // hc_w1: (1024 x 36864) @ (36864 x 512), split-K=16 (hc_b1 cancels in BN)
    tf32gemm_k<false, false, true, false><<<dim3(4, 8, SPLITZ), 256>>>(
        p_outb, hc_w1, p_part, nullptr, 1024, 512, 36864 / SPLITZ, 36864, 512, 512);
    reduce_part_k<<<2048, 256>>>(p_part, p_h1);

    bnstats_k<<<512, 256>>>(p_h1, 512, p_mean1, p_rstd1);
    bngelu_k<<<2048, 256>>>(p_h1, 512, p_mean1, p_rstd1, bn1_g, bn1_b);

    // hc_w2 (hc_b2 cancels in BN)
    tf32gemm_k<false, false, false, false><<<dim3(2, 8), 256>>>(
        p_h1, hc_w2, p_h2, nullptr, 1024, 256, 512, 512, 256, 256);
    bnstats_k<<<256, 256>>>(p_h2, 256, p_mean2, p_rstd2);
    bngelu_k<<<1024, 256>>>(p_h2, 256, p_mean2, p_rstd2, bn2_g, bn2_b);

    // final linear + softmax
    final_k<<<BB, 32>>>(p_h2, hc_w3, hc_b3, (float*)d_out);
}

// round 4
// speedup vs baseline: 3.7653x; 1.1357x over previous
#include <cuda_runtime.h>
#include <cuda_bf16.h>
#include <cstdint>
#include <cstddef>

// ---------------- constants ----------------
#define BB 1024
#define XDIM 62
#define TWIN 10
#define INCH 128
#define MIDD 256
#define OUTD 512
#define KTOT 7936          // 62*128
#define SPLITZ 16

// region permutation (concatenation of REGIONS index lists; partitions 0..61)
__constant__ int c_perm[62] = {
    0,1,2,3,4,
    5,6,7,14,15,16,
    8,9,10,17,18,19,
    11,12,13,20,21,22,
    23,24,25,32,33,34,
    26,27,28,35,36,37,
    29,30,31,38,39,40,
    41,42,43,50,51,57,
    44,45,46,52,53,54,58,59,60,
    47,48,49,55,56,61};
__constant__ int c_koff[10] = {0,640,1408,2176,2944,3712,4480,5248,6016,7168};
__constant__ int c_L[10]    = {5,6,6,6,6,6,6,6,9,6};

// ---------------- scratch (device globals; no allocation allowed) ----------------
__device__ float d_gcat[BB*XDIM*384];      // [g | Ag | A2g]
__device__ float d_g1[BB*XDIM*512];
__device__ float d_regbuf[BB*KTOT];
__device__ float d_wT[KTOT*256];
__device__ float d_g2cat[BB*10*768];       // [g2in | A1 g2in | A1^2 g2in]
__device__ float d_g2[BB*10*512];
__device__ float d_outb[BB*72*512];
__device__ float d_part[SPLITZ*BB*512];
__device__ float d_h1[BB*512];
__device__ float d_h2[BB*256];
__device__ float d_A2[62*62];
__device__ float d_A1s[100];
__device__ float d_mean1[512], d_rstd1[512];
__device__ float d_mean2[256], d_rstd2[256];

// ---------------- ptx helpers ----------------
__device__ __forceinline__ uint32_t smem_u32(const void* p) {
    return (uint32_t)__cvta_generic_to_shared(p);
}
__device__ __forceinline__ void cpasync16(uint32_t s, const void* g) {
    asm volatile("cp.async.cg.shared.global [%0], [%1], 16;" :: "r"(s), "l"(g));
}
__device__ __forceinline__ void cp_commit() {
    asm volatile("cp.async.commit_group;");
}
__device__ __forceinline__ void cp_wait1() {
    asm volatile("cp.async.wait_group 1;");
}

__device__ __forceinline__ void mma8(float* d, const uint32_t* a, uint32_t b0, uint32_t b1) {
    asm volatile(
        "mma.sync.aligned.m16n8k8.row.col.f32.tf32.tf32.f32 "
        "{%0,%1,%2,%3},{%4,%5,%6,%7},{%8,%9},{%0,%1,%2,%3};\n"
        : "+f"(d[0]), "+f"(d[1]), "+f"(d[2]), "+f"(d[3])
        : "r"(a[0]), "r"(a[1]), "r"(a[2]), "r"(a[3]), "r"(b0), "r"(b1));
}

// ---------------- tf32 tensor-core GEMM (cp.async double-buffered) ----------------
// CTA tile 128x128, K-step 16, 256 threads = 8 warps (4M x 2N), warp tile 32x64.
// fp32 bits fed directly to tf32 mma (HW truncation, CUTLASS 1xTF32 style).
// grid: x = col tiles, y = row tiles, z = split-K chunk or region index.
// Requires M%128==0, N%128==0, K%16==0.
template<bool RELU, bool BIAS, bool SPLITK, bool REGION>
__global__ __launch_bounds__(256, 2)
void tf32gemm_k(const float* __restrict__ A, const float* __restrict__ Bm,
                float* __restrict__ C, const float* __restrict__ bias,
                int M, int N, int K, int lda, int ldb, int ldc) {
    __shared__ float As[2][128][20];   // padded: conflict-free frag loads
    __shared__ float Bs[2][16][136];

    int tid = threadIdx.x;

    if (REGION) {
        int rz = blockIdx.z;
        A    += c_koff[rz];
        Bm   += (size_t)c_koff[rz] * ldb;
        C    += rz * 768;
        if (BIAS) bias += rz * MIDD;
        K = c_L[rz] * 128;
    }
    if (SPLITK) {
        A  += (size_t)blockIdx.z * K;
        Bm += (size_t)blockIdx.z * K * ldb;
        C  += (size_t)blockIdx.z * (size_t)M * N;
    }

    int row0 = blockIdx.y * 128, col0 = blockIdx.x * 128;

    // gmem staging indices
    int ar = tid >> 1, aseg = (tid & 1) * 8;     // A: 128 rows x 16 k
    int br = tid >> 4, bc = (tid & 15) * 8;      // B: 16 k x 128 n
    const float* Ap = A + (size_t)(row0 + ar) * lda + aseg;
    const float* Bp = Bm + (size_t)br * ldb + col0 + bc;

    int lane = tid & 31, wid = tid >> 5;
    int wm = wid >> 1, wn = wid & 1;
    int g = lane >> 2, t = lane & 3;

    float acc[2][8][4] = {};

    int nk = K >> 4;

    // stage-0 prologue
    {
        uint32_t a_s = smem_u32(&As[0][ar][aseg]);
        cpasync16(a_s, Ap);
        cpasync16(a_s + 16, Ap + 4);
        uint32_t b_s = smem_u32(&Bs[0][br][bc]);
        cpasync16(b_s, Bp);
        cpasync16(b_s + 16, Bp + 4);
        cp_commit();
    }

    for (int k = 0; k < nk; k++) {
        int cur = k & 1;
        // issue next stage (possibly empty group to keep accounting uniform)
        if (k + 1 < nk) {
            int nxt = cur ^ 1;
            int ko = (k + 1) << 4;
            uint32_t a_s = smem_u32(&As[nxt][ar][aseg]);
            cpasync16(a_s, Ap + ko);
            cpasync16(a_s + 16, Ap + ko + 4);
            uint32_t b_s = smem_u32(&Bs[nxt][br][bc]);
            cpasync16(b_s, Bp + (size_t)ko * ldb);
            cpasync16(b_s + 16, Bp + (size_t)ko * ldb + 4);
        }
        cp_commit();
        cp_wait1();            // stage k complete (newest group may be in flight)
        __syncthreads();

#pragma unroll
        for (int kt = 0; kt < 16; kt += 8) {
            uint32_t a[2][4];
#pragma unroll
            for (int mm = 0; mm < 2; mm++) {
                int r = wm * 32 + mm * 16 + g;
                a[mm][0] = __float_as_uint(As[cur][r][kt + t]);
                a[mm][1] = __float_as_uint(As[cur][r + 8][kt + t]);
                a[mm][2] = __float_as_uint(As[cur][r][kt + t + 4]);
                a[mm][3] = __float_as_uint(As[cur][r + 8][kt + t + 4]);
            }
#pragma unroll
            for (int nn = 0; nn < 8; nn++) {
                int cb = wn * 64 + nn * 8 + g;
                uint32_t b0 = __float_as_uint(Bs[cur][kt + t][cb]);
                uint32_t b1 = __float_as_uint(Bs[cur][kt + t + 4][cb]);
                mma8(acc[0][nn], a[0], b0, b1);
                mma8(acc[1][nn], a[1], b0, b1);
            }
        }
        __syncthreads();   // all warps done with buf[cur] before it is refilled
    }

    // epilogue
#pragma unroll
    for (int mm = 0; mm < 2; mm++) {
        int r = row0 + wm * 32 + mm * 16 + g;
#pragma unroll
        for (int nn = 0; nn < 8; nn++) {
            int c = col0 + wn * 64 + nn * 8 + 2 * t;
            float v0 = acc[mm][nn][0], v1 = acc[mm][nn][1];
            float v2 = acc[mm][nn][2], v3 = acc[mm][nn][3];
            if (BIAS) {
                float q0 = bias[c], q1 = bias[c + 1];
                v0 += q0; v1 += q1; v2 += q0; v3 += q1;
            }
            if (RELU) {
                v0 = fmaxf(v0, 0.f); v1 = fmaxf(v1, 0.f);
                v2 = fmaxf(v2, 0.f); v3 = fmaxf(v3, 0.f);
            }
            *(float2*)&C[(size_t)r * ldc + c] = make_float2(v0, v1);
            *(float2*)&C[(size_t)(r + 8) * ldc + c] = make_float2(v2, v3);
        }
    }
}

// ---------------- small prep kernels ----------------
__global__ void a2_k(const float* __restrict__ A, float* __restrict__ A2) {
    int i = blockIdx.x * blockDim.x + threadIdx.x;
    if (i >= 62*62) return;
    int r = i / 62, c = i % 62;
    float s = 0.f;
    for (int m = 0; m < 62; m++) s += A[r*62+m] * A[m*62+c];
    A2[i] = s;
}

__global__ void a1sq_k(const float* __restrict__ A1, float* __restrict__ A1s) {
    int i = threadIdx.x;
    if (i >= 100) return;
    int r = i / 10, c = i % 10;
    float s = 0.f;
    for (int m = 0; m < 10; m++) s += A1[r*10+m] * A1[m*10+c];
    A1s[i] = s;
}

struct RWPtrs { const float* p[10]; };

// transpose region weights rw_i[m,c,l] -> wT[(koff_i + l*128 + c)*256 + m]
__global__ void wt_k(RWPtrs rw, float* __restrict__ wT) {
    int e = blockIdx.x * 256 + threadIdx.x;   // < 7936*256
    int m = e & 255;
    int kidx = e >> 8;
    int i = 0;
#pragma unroll
    for (int q = 1; q < 10; q++) if (kidx >= c_koff[q]) i = q;
    int d = kidx - c_koff[i];
    int l = d >> 7, c = d & 127;
    wT[(size_t)kidx * 256 + m] = rw.p[i][(m * 128 + c) * c_L[i] + l];
}

// fused: variance(ddof=1) over TWIN + tfe einsum + exp gate -> g (slice 0 of gcat)
__global__ void tfe_k(const float* __restrict__ x, const float* __restrict__ w,
                      const float* __restrict__ bvec, float* __restrict__ gcat) {
    int bc = blockIdx.x;           // b*62 + c
    int c = bc % 62;
    int t = threadIdx.x;           // 0..127
    const float* xp = x + (size_t)bc * TWIN * INCH + t;
    float s1 = 0.f, s2 = 0.f, ws = 0.f;
#pragma unroll
    for (int i = 0; i < TWIN; i++) {
        float v = xp[(size_t)i * INCH];
        s1 += v; s2 += v * v;
        ws += v * w[c * TWIN + i];
    }
    float var = (s2 - s1 * s1 * 0.1f) * (1.f / 9.f);   // ddof=1
    float g = (ws + bvec[c]) * expf(-var);
    gcat[(size_t)bc * 384 + t] = g;
}

// compute Ag, A^2 g into slices 1,2 of gcat (register-blocked 4 rows)
__global__ void applyA_k(const float* __restrict__ A, const float* __restrict__ A2,
                         float* __restrict__ gcat) {
    __shared__ float gs[62][128];
    int b = blockIdx.x;
    int t = threadIdx.x;   // 128
    int yy = threadIdx.y;  // 4
    for (int n = yy; n < 62; n += 4)
        gs[n][t] = gcat[((size_t)b * 62 + n) * 384 + t];
    __syncthreads();
#pragma unroll
    for (int base = 0; base < 64; base += 16) {
        int n = base + yy * 4;
        float s1[4] = {0,0,0,0}, s2[4] = {0,0,0,0};
        bool val[4];
#pragma unroll
        for (int q = 0; q < 4; q++) val[q] = (n + q) < 62;
        for (int m = 0; m < 62; m++) {
            float v = gs[m][t];
#pragma unroll
            for (int q = 0; q < 4; q++) {
                if (val[q]) {
                    s1[q] += A[(n + q) * 62 + m] * v;
                    s2[q] += A2[(n + q) * 62 + m] * v;
                }
            }
        }
#pragma unroll
        for (int q = 0; q < 4; q++) {
            if (val[q]) {
                gcat[((size_t)b * 62 + n + q) * 384 + 128 + t] = s1[q];
                gcat[((size_t)b * 62 + n + q) * 384 + 256 + t] = s2[q];
            }
        }
    }
}

// gather permuted region rows: regbuf[b, j] = g[b, perm[j/128], j%128]
__global__ void gather_k(const float* __restrict__ gcat, float* __restrict__ regbuf) {
    size_t e = (size_t)blockIdx.x * 256 + threadIdx.x;   // < 1024*7936
    int b = (int)(e / KTOT);
    int j = (int)(e % KTOT);
    int l = j >> 7, c = j & 127;
    regbuf[e] = gcat[((size_t)b * 62 + c_perm[l]) * 384 + c];
}

// A1, A1^2 apply for cheby2 (slices 1,2 of g2cat)
__global__ void applyA1_k(const float* __restrict__ A1, const float* __restrict__ A1s,
                          float* __restrict__ g2cat) {
    int b = blockIdx.x;
    int t = threadIdx.x;   // 256
    float v[10];
#pragma unroll
    for (int m = 0; m < 10; m++) v[m] = g2cat[((size_t)b * 10 + m) * 768 + t];
#pragma unroll
    for (int n = 0; n < 10; n++) {
        float s1 = 0.f, s2 = 0.f;
#pragma unroll
        for (int m = 0; m < 10; m++) {
            s1 += A1[n * 10 + m] * v[m];
            s2 += A1s[n * 10 + m] * v[m];
        }
        g2cat[((size_t)b * 10 + n) * 768 + 256 + t] = s1;
        g2cat[((size_t)b * 10 + n) * 768 + 512 + t] = s2;
    }
}

// ---------------- softmax gate (smem-staged, single global read) ----------------
__global__ void softgate_k(const float* __restrict__ g1, const float* __restrict__ g2,
                           const float* __restrict__ bg, const float* __restrict__ cg,
                           float* __restrict__ outb) {
    extern __shared__ float sm[];   // 72 * 512
    int b = blockIdx.x;
    int o = threadIdx.x;   // 512
    float Bg = *bg, Cg = *cg;
#pragma unroll 2
    for (int s = 0; s < 62; s++)
        sm[s * 512 + o] = g1[((size_t)b * 62 + s) * 512 + o];
#pragma unroll
    for (int s = 0; s < 10; s++)
        sm[(62 + s) * 512 + o] = g2[((size_t)b * 10 + s) * 512 + o];
    __syncthreads();
    float M = -1e30f, S = 0.f;
#pragma unroll 2
    for (int s = 0; s < 72; s++) {
        float a = ((s < 62) ? Bg : Cg) * sm[s * 512 + o];
        float nM = fmaxf(M, a);
        S = S * expf(M - nM) + expf(a - nM);
        M = nM;
    }
    float inv = 1.f / S;
#pragma unroll 2
    for (int s = 0; s < 72; s++) {
        float v = sm[s * 512 + o];
        float a = ((s < 62) ? Bg : Cg) * v;
        outb[(size_t)b * 36864 + s * 512 + o] = expf(a - M) * inv * v;
    }
}

// ---------------- split-K reduce (bias cancels in BN; skipped) ----------------
__global__ void reduce_part_k(const float* __restrict__ part, float* __restrict__ out) {
    int i = blockIdx.x * 256 + threadIdx.x;   // < 1024*512
    float s = 0.f;
#pragma unroll
    for (int z = 0; z < SPLITZ; z++) s += part[(size_t)z * (BB * 512) + i];
    out[i] = s;
}

// ---------------- batch-norm stats + bn*gelu ----------------
__global__ void bnstats_k(const float* __restrict__ h, int F,
                          float* __restrict__ mean, float* __restrict__ rstd) {
    __shared__ float sh1[256], sh2[256];
    int j = blockIdx.x;
    float s1 = 0.f, s2 = 0.f;
    for (int b = threadIdx.x; b < BB; b += 256) {
        float v = h[(size_t)b * F + j];
        s1 += v; s2 += v * v;
    }
    sh1[threadIdx.x] = s1; sh2[threadIdx.x] = s2;
    __syncthreads();
    for (int o = 128; o; o >>= 1) {
        if (threadIdx.x < o) {
            sh1[threadIdx.x] += sh1[threadIdx.x + o];
            sh2[threadIdx.x] += sh2[threadIdx.x + o];
        }
        __syncthreads();
    }
    if (threadIdx.x == 0) {
        float mu = sh1[0] * (1.f / BB);
        float var = sh2[0] * (1.f / BB) - mu * mu;
        mean[j] = mu;
        rstd[j] = rsqrtf(var + 1e-5f);
    }
}

__global__ void bngelu_k(float* __restrict__ h, int F,
                         const float* __restrict__ mean, const float* __restrict__ rstd,
                         const float* __restrict__ gam, const float* __restrict__ bet) {
    int i = blockIdx.x * 256 + threadIdx.x;
    int j = i % F;
    float v = (h[i] - mean[j]) * rstd[j] * gam[j] + bet[j];
    h[i] = 0.5f * v * (1.f + erff(v * 0.70710678118654752f));
}

// ---------------- final linear + softmax ----------------
__global__ void final_k(const float* __restrict__ h2, const float* __restrict__ w3,
                        const float* __restrict__ b3, float* __restrict__ out) {
    int b = blockIdx.x;
    int lane = threadIdx.x;   // 32
    float acc[4] = {0.f, 0.f, 0.f, 0.f};
    for (int k = lane; k < 256; k += 32) {
        float v = h2[(size_t)b * 256 + k];
#pragma unroll
        for (int j = 0; j < 4; j++) acc[j] += v * w3[k * 4 + j];
    }
#pragma unroll
    for (int off = 16; off; off >>= 1)
#pragma unroll
        for (int j = 0; j < 4; j++)
            acc[j] += __shfl_down_sync(0xffffffffu, acc[j], off);
    if (lane == 0) {
        float l[4];
#pragma unroll
        for (int j = 0; j < 4; j++) l[j] = acc[j] + b3[j];
        float m = fmaxf(fmaxf(l[0], l[1]), fmaxf(l[2], l[3]));
        float e[4], s = 0.f;
#pragma unroll
        for (int j = 0; j < 4; j++) { e[j] = expf(l[j] - m); s += e[j]; }
        float inv = 1.f / s;
#pragma unroll
        for (int j = 0; j < 4; j++) out[b * 4 + j] = e[j] * inv;
    }
}

// ---------------- host ----------------
static float* sym(const void* s) {
    void* p = nullptr;
    cudaGetSymbolAddress(&p, s);
    return (float*)p;
}

extern "C" void kernel_launch(void* const* d_in, const int* in_sizes, int n_in,
                              void* d_out, int out_size) {
    const float* x        = (const float*)d_in[0];
    const float* tfe_w    = (const float*)d_in[1];
    const float* tfe_b    = (const float*)d_in[2];
    const float* cheby1_w = (const float*)d_in[3];
    const float* A        = (const float*)d_in[4];
    const float* cheby2_w = (const float*)d_in[5];
    const float* A1       = (const float*)d_in[6];
    const float* b_gate   = (const float*)d_in[7];
    const float* c_gate   = (const float*)d_in[8];

    const float *rw[10], *region_b, *hc_w1, *bn1_g, *bn1_b;
    const float *hc_w2, *bn2_g, *bn2_b, *hc_w3, *hc_b3;

    if (in_sizes[9] == 2560) {
        // dict insertion order: region_b..hc_b3 then rw1..rw10
        region_b = (const float*)d_in[9];
        hc_w1    = (const float*)d_in[10];
        bn1_g    = (const float*)d_in[12];
        bn1_b    = (const float*)d_in[13];
        hc_w2    = (const float*)d_in[14];
        bn2_g    = (const float*)d_in[16];
        bn2_b    = (const float*)d_in[17];
        hc_w3    = (const float*)d_in[18];
        hc_b3    = (const float*)d_in[19];
        for (int i = 0; i < 10; i++) rw[i] = (const float*)d_in[20 + i];
    } else {
        // reference signature order: rw1..rw10 then region_b..hc_b3
        for (int i = 0; i < 10; i++) rw[i] = (const float*)d_in[9 + i];
        region_b = (const float*)d_in[19];
        hc_w1    = (const float*)d_in[20];
        bn1_g    = (const float*)d_in[22];
        bn1_b    = (const float*)d_in[23];
        hc_w2    = (const float*)d_in[24];
        bn2_g    = (const float*)d_in[26];
        bn2_b    = (const float*)d_in[27];
        hc_w3    = (const float*)d_in[28];
        hc_b3    = (const float*)d_in[29];
    }

    float* p_gcat   = sym(d_gcat);
    float* p_g1     = sym(d_g1);
    float* p_regbuf = sym(d_regbuf);
    float* p_wT     = sym(d_wT);
    float* p_g2cat  = sym(d_g2cat);
    float* p_g2     = sym(d_g2);
    float* p_outb   = sym(d_outb);
    float* p_part   = sym(d_part);
    float* p_h1     = sym(d_h1);
    float* p_h2     = sym(d_h2);
    float* p_A2     = sym(d_A2);
    float* p_A1s    = sym(d_A1s);
    float* p_mean1  = sym(d_mean1);
    float* p_rstd1  = sym(d_rstd1);
    float* p_mean2  = sym(d_mean2);
    float* p_rstd2  = sym(d_rstd2);

    static bool attr_done = false;
    if (!attr_done) {
        cudaFuncSetAttribute(softgate_k, cudaFuncAttributeMaxDynamicSharedMemorySize,
                             72 * 512 * 4);
        attr_done = true;
    }

    // prep
    a2_k<<<16, 256>>>(A, p_A2);
    a1sq_k<<<1, 128>>>(A1, p_A1s);
    RWPtrs rwp;
    for (int i = 0; i < 10; i++) rwp.p[i] = rw[i];
    wt_k<<<KTOT, 256>>>(rwp, p_wT);

    // front-end fuse
    tfe_k<<<BB * XDIM, 128>>>(x, tfe_w, tfe_b, p_gcat);
    applyA_k<<<BB, dim3(128, 4)>>>(A, p_A2, p_gcat);

    // cheby1: (63488 x 384) @ (384 x 512) + relu   [tensor core tf32]
    tf32gemm_k<true, false, false, false><<<dim3(4, 496), 256>>>(
        p_gcat, cheby1_w, p_g1, nullptr, 63488, 512, 384, 384, 512, 512);

    // regions: batched 10 GEMMs (1024 x 256, K = L_i*128) + bias
    gather_k<<<BB * KTOT / 256, 256>>>(p_gcat, p_regbuf);
    tf32gemm_k<false, true, false, true><<<dim3(2, 8, 10), 256>>>(
        p_regbuf, p_wT, p_g2cat, region_b, 1024, 256, 0, KTOT, 256, 7680);

    // cheby2
    applyA1_k<<<BB, 256>>>(A1, p_A1s, p_g2cat);
    tf32gemm_k<true, false, false, false><<<dim3(4, 80), 256>>>(
        p_g2cat, cheby2_w, p_g2, nullptr, 10240, 512, 768, 768, 512, 512);

    // softmax gate -> (B, 36864)
    softgate_k<<<BB, 512, 72 * 512 * 4>>>(p_g1, p_g2, b_gate, c_gate, p_outb);

    // hc_w1: (1024 x 36864) @ (36864 x 512), split-K=16 (hc_b1 cancels in BN)
    tf32gemm_k<false, false, true, false><<<dim3(4, 8, SPLITZ), 256>>>(
        p_outb, hc_w1, p_part, nullptr, 1024, 512, 36864 / SPLITZ, 36864, 512, 512);
    reduce_part_k<<<2048, 256>>>(p_part, p_h1);

    bnstats_k<<<512, 256>>>(p_h1, 512, p_mean1, p_rstd1);
    bngelu_k<<<2048, 256>>>(p_h1, 512, p_mean1, p_rstd1, bn1_g, bn1_b);

    // hc_w2 (hc_b2 cancels in BN)
    tf32gemm_k<false, false, false, false><<<dim3(2, 8), 256>>>(
        p_h1, hc_w2, p_h2, nullptr, 1024, 256, 512, 512, 256, 256);
    bnstats_k<<<256, 256>>>(p_h2, 256, p_mean2, p_rstd2);
    bngelu_k<<<1024, 256>>>(p_h2, 256, p_mean2, p_rstd2, bn2_g, bn2_b);

    // final linear + softmax
    final_k<<<BB, 32>>>(p_h2, hc_w3, hc_b3, (float*)d_out);
}

// round 6
// speedup vs baseline: 4.9920x; 1.3258x over previous
#include <cuda_runtime.h>
#include <cuda_bf16.h>
#include <cstdint>
#include <cstddef>

// ---------------- constants ----------------
#define BB 1024
#define XDIM 62
#define TWIN 10
#define INCH 128
#define MIDD 256
#define OUTD 512
#define KTOT 7936          // 62*128
#define SPLITZ 16

typedef __nv_bfloat16 bf16;

// region permutation (concatenation of REGIONS index lists; partitions 0..61)
__constant__ int c_perm[62] = {
    0,1,2,3,4,
    5,6,7,14,15,16,
    8,9,10,17,18,19,
    11,12,13,20,21,22,
    23,24,25,32,33,34,
    26,27,28,35,36,37,
    29,30,31,38,39,40,
    41,42,43,50,51,57,
    44,45,46,52,53,54,58,59,60,
    47,48,49,55,56,61};
__constant__ int c_koff[10] = {0,640,1408,2176,2944,3712,4480,5248,6016,7168};
__constant__ int c_L[10]    = {5,6,6,6,6,6,6,6,9,6};

// ---------------- scratch (device globals; no allocation allowed) ----------------
__device__ bf16  d_gcat[BB*XDIM*384];      // [g | Ag | A2g]  bf16 [M][K]
__device__ bf16  d_g1[BB*XDIM*512];        // cheby1 out bf16
__device__ bf16  d_regbuf[BB*KTOT];
__device__ float d_wTf[KTOT*256];          // fp32 [k][m] staging
__device__ bf16  d_wrT[256*KTOT];          // bf16 [m][k]
__device__ bf16  d_c1T[512*384];           // cheby1_w^T bf16 [N][K]
__device__ bf16  d_c2T[512*768];
__device__ bf16  d_w1T[512*36864];
__device__ bf16  d_w2T[256*512];
__device__ bf16  d_g2cat[BB*10*768];       // [g2in | A1 g2in | A1^2 g2in] bf16
__device__ bf16  d_g2[BB*10*512];
__device__ bf16  d_outb[BB*72*512];
__device__ float d_part[SPLITZ*BB*512];
__device__ float d_h1[BB*512];
__device__ bf16  d_h1b[BB*512];
__device__ float d_h2[BB*256];
__device__ float d_A2[62*62];
__device__ float d_A1s[100];
__device__ float d_mean1[512], d_rstd1[512];
__device__ float d_mean2[256], d_rstd2[256];

// ---------------- ptx helpers ----------------
__device__ __forceinline__ uint32_t smem_u32(const void* p) {
    return (uint32_t)__cvta_generic_to_shared(p);
}
__device__ __forceinline__ void cpasync16(uint32_t s, const void* g) {
    asm volatile("cp.async.cg.shared.global [%0], [%1], 16;" :: "r"(s), "l"(g));
}
__device__ __forceinline__ void cp_commit() {
    asm volatile("cp.async.commit_group;");
}
__device__ __forceinline__ void cp_wait1() {
    asm volatile("cp.async.wait_group 1;");
}

__device__ __forceinline__ void mma16(float* d, const uint32_t* a, uint32_t b0, uint32_t b1) {
    asm volatile(
        "mma.sync.aligned.m16n8k16.row.col.f32.bf16.bf16.f32 "
        "{%0,%1,%2,%3},{%4,%5,%6,%7},{%8,%9},{%0,%1,%2,%3};\n"
        : "+f"(d[0]), "+f"(d[1]), "+f"(d[2]), "+f"(d[3])
        : "r"(a[0]), "r"(a[1]), "r"(a[2]), "r"(a[3]), "r"(b0), "r"(b1));
}

// ---------------- bf16 tensor-core GEMM (cp.async double-buffered) ----------------
// A: bf16 [M][lda] row-major.  B: bf16 [N][ldb] (i.e. weights transposed, K contiguous).
// CTA tile 128x128, K-step 32, 256 threads = 8 warps (4M x 2N), warp tile 32x64.
// grid: x = col tiles, y = row tiles, z = split-K chunk or region index.
// Requires M%128==0, N%128==0, K%32==0.
template<bool RELU, bool BIAS, bool SPLITK, bool REGION, bool OUTBF>
__global__ __launch_bounds__(256, 2)
void bf16gemm_k(const bf16* __restrict__ A, const bf16* __restrict__ Bt,
                void* __restrict__ Cv, const float* __restrict__ bias,
                int M, int N, int K, int lda, int ldb, int ldc) {
    __shared__ bf16 As[2][128][40];   // 32 k + 8 pad (80B rows, conflict-free)
    __shared__ bf16 Bs[2][128][40];   // [n][k]

    int tid = threadIdx.x;

    bf16*  Cb = (bf16*)Cv;
    float* Cf = (float*)Cv;

    if (REGION) {
        int rz = blockIdx.z;
        A    += c_koff[rz];
        Bt   += c_koff[rz];           // k offset within [n][k]
        Cb   += rz * 768;
        if (BIAS) bias += rz * MIDD;
        K = c_L[rz] * 128;
    }
    if (SPLITK) {
        A  += (size_t)blockIdx.z * K;
        Bt += (size_t)blockIdx.z * K;
        Cf += (size_t)blockIdx.z * (size_t)M * N;
    }

    int row0 = blockIdx.y * 128, col0 = blockIdx.x * 128;

    // gmem staging: each thread copies 32B (2x16B) of A and of B per stage
    int sr = tid >> 1, ks = (tid & 1) * 16;      // row 0..127, k-seg 0/16
    const bf16* Ap = A + (size_t)(row0 + sr) * lda + ks;
    const bf16* Bp = Bt + (size_t)(col0 + sr) * ldb + ks;

    int lane = tid & 31, wid = tid >> 5;
    int wm = wid >> 1, wn = wid & 1;
    int g = lane >> 2, t2 = (lane & 3) * 2;

    float acc[2][8][4] = {};
    int nk = K >> 5;

    {
        uint32_t a_s = smem_u32(&As[0][sr][ks]);
        cpasync16(a_s, Ap);
        cpasync16(a_s + 16, Ap + 8);
        uint32_t b_s = smem_u32(&Bs[0][sr][ks]);
        cpasync16(b_s, Bp);
        cpasync16(b_s + 16, Bp + 8);
        cp_commit();
    }

    for (int k = 0; k < nk; k++) {
        int cur = k & 1;
        if (k + 1 < nk) {
            int nxt = cur ^ 1;
            int ko = (k + 1) << 5;
            uint32_t a_s = smem_u32(&As[nxt][sr][ks]);
            cpasync16(a_s, Ap + ko);
            cpasync16(a_s + 16, Ap + ko + 8);
            uint32_t b_s = smem_u32(&Bs[nxt][sr][ks]);
            cpasync16(b_s, Bp + ko);
            cpasync16(b_s + 16, Bp + ko + 8);
        }
        cp_commit();
        cp_wait1();
        __syncthreads();

#pragma unroll
        for (int kt = 0; kt < 32; kt += 16) {
            uint32_t a[2][4];
#pragma unroll
            for (int mm = 0; mm < 2; mm++) {
                int r = wm * 32 + mm * 16 + g;
                a[mm][0] = *(const uint32_t*)&As[cur][r][kt + t2];
                a[mm][1] = *(const uint32_t*)&As[cur][r + 8][kt + t2];
                a[mm][2] = *(const uint32_t*)&As[cur][r][kt + t2 + 8];
                a[mm][3] = *(const uint32_t*)&As[cur][r + 8][kt + t2 + 8];
            }
#pragma unroll
            for (int nn = 0; nn < 8; nn++) {
                int cb = wn * 64 + nn * 8 + g;
                uint32_t b0 = *(const uint32_t*)&Bs[cur][cb][kt + t2];
                uint32_t b1 = *(const uint32_t*)&Bs[cur][cb][kt + t2 + 8];
                mma16(acc[0][nn], a[0], b0, b1);
                mma16(acc[1][nn], a[1], b0, b1);
            }
        }
        __syncthreads();
    }

    // epilogue
#pragma unroll
    for (int mm = 0; mm < 2; mm++) {
        int r = row0 + wm * 32 + mm * 16 + g;
#pragma unroll
        for (int nn = 0; nn < 8; nn++) {
            int c = col0 + wn * 64 + nn * 8 + t2;
            float v0 = acc[mm][nn][0], v1 = acc[mm][nn][1];
            float v2 = acc[mm][nn][2], v3 = acc[mm][nn][3];
            if (BIAS) {
                float q0 = bias[c], q1 = bias[c + 1];
                v0 += q0; v1 += q1; v2 += q0; v3 += q1;
            }
            if (RELU) {
                v0 = fmaxf(v0, 0.f); v1 = fmaxf(v1, 0.f);
                v2 = fmaxf(v2, 0.f); v3 = fmaxf(v3, 0.f);
            }
            if (OUTBF) {
                __nv_bfloat162* p0 = (__nv_bfloat162*)&Cb[(size_t)r * ldc + c];
                __nv_bfloat162* p1 = (__nv_bfloat162*)&Cb[(size_t)(r + 8) * ldc + c];
                *p0 = __floats2bfloat162_rn(v0, v1);
                *p1 = __floats2bfloat162_rn(v2, v3);
            } else {
                *(float2*)&Cf[(size_t)r * ldc + c] = make_float2(v0, v1);
                *(float2*)&Cf[(size_t)(r + 8) * ldc + c] = make_float2(v2, v3);
            }
        }
    }
}

// ---------------- transpose + convert: fp32 [R][C] -> bf16 [C][R] ----------------
__global__ void cvtT_k(const float* __restrict__ src, bf16* __restrict__ dst,
                       int R, int C) {
    __shared__ float tile[32][33];
    int rb = blockIdx.y * 32, cb = blockIdx.x * 32;
#pragma unroll
    for (int i = 0; i < 32; i += 8)
        tile[threadIdx.y + i][threadIdx.x] =
            src[(size_t)(rb + threadIdx.y + i) * C + cb + threadIdx.x];
    __syncthreads();
#pragma unroll
    for (int i = 0; i < 32; i += 8)
        dst[(size_t)(cb + threadIdx.y + i) * R + rb + threadIdx.x] =
            __float2bfloat16(tile[threadIdx.x][threadIdx.y + i]);
}

// ---------------- small prep kernels ----------------
__global__ void a2_k(const float* __restrict__ A, float* __restrict__ A2) {
    int i = blockIdx.x * blockDim.x + threadIdx.x;
    if (i >= 62*62) return;
    int r = i / 62, c = i % 62;
    float s = 0.f;
    for (int m = 0; m < 62; m++) s += A[r*62+m] * A[m*62+c];
    A2[i] = s;
}

__global__ void a1sq_k(const float* __restrict__ A1, float* __restrict__ A1s) {
    int i = threadIdx.x;
    if (i >= 100) return;
    int r = i / 10, c = i % 10;
    float s = 0.f;
    for (int m = 0; m < 10; m++) s += A1[r*10+m] * A1[m*10+c];
    A1s[i] = s;
}

struct RWPtrs { const float* p[10]; };

// transpose region weights rw_i[m,c,l] -> wTf[(koff_i + l*128 + c)*256 + m] (fp32, coalesced)
__global__ void wt_k(RWPtrs rw, float* __restrict__ wT) {
    int e = blockIdx.x * 256 + threadIdx.x;   // < 7936*256
    int m = e & 255;
    int kidx = e >> 8;
    int i = 0;
#pragma unroll
    for (int q = 1; q < 10; q++) if (kidx >= c_koff[q]) i = q;
    int d = kidx - c_koff[i];
    int l = d >> 7, c = d & 127;
    wT[(size_t)kidx * 256 + m] = rw.p[i][(m * 128 + c) * c_L[i] + l];
}

// fused: variance(ddof=1) over TWIN + tfe einsum + exp gate -> g (slice 0, bf16)
__global__ void tfe_k(const float* __restrict__ x, const float* __restrict__ w,
                      const float* __restrict__ bvec, bf16* __restrict__ gcat) {
    int bc = blockIdx.x;           // b*62 + c
    int c = bc % 62;
    int t = threadIdx.x;           // 0..127
    const float* xp = x + (size_t)bc * TWIN * INCH + t;
    float s1 = 0.f, s2 = 0.f, ws = 0.f;
#pragma unroll
    for (int i = 0; i < TWIN; i++) {
        float v = xp[(size_t)i * INCH];
        s1 += v; s2 += v * v;
        ws += v * w[c * TWIN + i];
    }
    float var = (s2 - s1 * s1 * 0.1f) * (1.f / 9.f);   // ddof=1
    float g = (ws + bvec[c]) * expf(-var);
    gcat[(size_t)bc * 384 + t] = __float2bfloat16(g);
}

// compute Ag, A^2 g into slices 1,2 of gcat (bf16 in/out, fp32 math)
__global__ void applyA_k(const float* __restrict__ A, const float* __restrict__ A2,
                         bf16* __restrict__ gcat) {
    __shared__ float gs[62][128];
    int b = blockIdx.x;
    int t = threadIdx.x;   // 128
    int yy = threadIdx.y;  // 4
    for (int n = yy; n < 62; n += 4)
        gs[n][t] = __bfloat162float(gcat[((size_t)b * 62 + n) * 384 + t]);
    __syncthreads();
#pragma unroll
    for (int base = 0; base < 64; base += 16) {
        int n = base + yy * 4;
        float s1[4] = {0,0,0,0}, s2[4] = {0,0,0,0};
        bool val[4];
#pragma unroll
        for (int q = 0; q < 4; q++) val[q] = (n + q) < 62;
        for (int m = 0; m < 62; m++) {
            float v = gs[m][t];
#pragma unroll
            for (int q = 0; q < 4; q++) {
                if (val[q]) {
                    s1[q] += A[(n + q) * 62 + m] * v;
                    s2[q] += A2[(n + q) * 62 + m] * v;
                }
            }
        }
#pragma unroll
        for (int q = 0; q < 4; q++) {
            if (val[q]) {
                gcat[((size_t)b * 62 + n + q) * 384 + 128 + t] = __float2bfloat16(s1[q]);
                gcat[((size_t)b * 62 + n + q) * 384 + 256 + t] = __float2bfloat16(s2[q]);
            }
        }
    }
}

// gather permuted region rows (u32 = 2 bf16 at a time)
__global__ void gather_k(const bf16* __restrict__ gcat, bf16* __restrict__ regbuf) {
    size_t e = (size_t)blockIdx.x * 256 + threadIdx.x;   // < 1024*3968
    int b = (int)(e / (KTOT / 2));
    int j = (int)(e % (KTOT / 2));                       // u32 index in row
    int l = j >> 6, cp = j & 63;
    const uint32_t* src = (const uint32_t*)&gcat[((size_t)b * 62 + c_perm[l]) * 384 + cp * 2];
    ((uint32_t*)regbuf)[e] = *src;
}

// A1, A1^2 apply for cheby2 (slices 1,2 of g2cat, bf16)
__global__ void applyA1_k(const float* __restrict__ A1, const float* __restrict__ A1s,
                          bf16* __restrict__ g2cat) {
    int b = blockIdx.x;
    int t = threadIdx.x;   // 256
    float v[10];
#pragma unroll
    for (int m = 0; m < 10; m++)
        v[m] = __bfloat162float(g2cat[((size_t)b * 10 + m) * 768 + t]);
#pragma unroll
    for (int n = 0; n < 10; n++) {
        float s1 = 0.f, s2 = 0.f;
#pragma unroll
        for (int m = 0; m < 10; m++) {
            s1 += A1[n * 10 + m] * v[m];
            s2 += A1s[n * 10 + m] * v[m];
        }
        g2cat[((size_t)b * 10 + n) * 768 + 256 + t] = __float2bfloat16(s1);
        g2cat[((size_t)b * 10 + n) * 768 + 512 + t] = __float2bfloat16(s2);
    }
}

// ---------------- softmax gate (bf16 in, bf16 out) ----------------
__global__ void softgate_k(const bf16* __restrict__ g1, const bf16* __restrict__ g2,
                           const float* __restrict__ bg, const float* __restrict__ cg,
                           bf16* __restrict__ outb) {
    extern __shared__ float sm[];   // 72 * 512
    int b = blockIdx.x;
    int o = threadIdx.x;   // 512
    float Bg = *bg, Cg = *cg;
#pragma unroll 2
    for (int s = 0; s < 62; s++)
        sm[s * 512 + o] = __bfloat162float(g1[((size_t)b * 62 + s) * 512 + o]);
#pragma unroll
    for (int s = 0; s < 10; s++)
        sm[(62 + s) * 512 + o] = __bfloat162float(g2[((size_t)b * 10 + s) * 512 + o]);
    __syncthreads();
    float M = -1e30f, S = 0.f;
#pragma unroll 2
    for (int s = 0; s < 72; s++) {
        float a = ((s < 62) ? Bg : Cg) * sm[s * 512 + o];
        float nM = fmaxf(M, a);
        S = S * expf(M - nM) + expf(a - nM);
        M = nM;
    }
    float inv = 1.f / S;
#pragma unroll 2
    for (int s = 0; s < 72; s++) {
        float v = sm[s * 512 + o];
        float a = ((s < 62) ? Bg : Cg) * v;
        outb[(size_t)b * 36864 + s * 512 + o] = __float2bfloat16(expf(a - M) * inv * v);
    }
}

// ---------------- split-K reduce ----------------
__global__ void reduce_part_k(const float* __restrict__ part, float* __restrict__ out) {
    int i = blockIdx.x * 256 + threadIdx.x;   // < 1024*512
    float s = 0.f;
#pragma unroll
    for (int z = 0; z < SPLITZ; z++) s += part[(size_t)z * (BB * 512) + i];
    out[i] = s;
}

// ---------------- batch-norm stats + bn*gelu ----------------
__global__ void bnstats_k(const float* __restrict__ h, int F,
                          float* __restrict__ mean, float* __restrict__ rstd) {
    __shared__ float sh1[256], sh2[256];
    int j = blockIdx.x;
    float s1 = 0.f, s2 = 0.f;
    for (int b = threadIdx.x; b < BB; b += 256) {
        float v = h[(size_t)b * F + j];
        s1 += v; s2 += v * v;
    }
    sh1[threadIdx.x] = s1; sh2[threadIdx.x] = s2;
    __syncthreads();
    for (int o = 128; o; o >>= 1) {
        if (threadIdx.x < o) {
            sh1[threadIdx.x] += sh1[threadIdx.x + o];
            sh2[threadIdx.x] += sh2[threadIdx.x + o];
        }
        __syncthreads();
    }
    if (threadIdx.x == 0) {
        float mu = sh1[0] * (1.f / BB);
        float var = sh2[0] * (1.f / BB) - mu * mu;
        mean[j] = mu;
        rstd[j] = rsqrtf(var + 1e-5f);
    }
}

__global__ void bngelu_k(float* __restrict__ h, int F,
                         const float* __restrict__ mean, const float* __restrict__ rstd,
                         const float* __restrict__ gam, const float* __restrict__ bet,
                         bf16* __restrict__ hb) {
    int i = blockIdx.x * 256 + threadIdx.x;
    int j = i % F;
    float v = (h[i] - mean[j]) * rstd[j] * gam[j] + bet[j];
    float r = 0.5f * v * (1.f + erff(v * 0.70710678118654752f));
    h[i] = r;
    if (hb) hb[i] = __float2bfloat16(r);
}

// ---------------- final linear + softmax ----------------
__global__ void final_k(const float* __restrict__ h2, const float* __restrict__ w3,
                        const float* __restrict__ b3, float* __restrict__ out) {
    int b = blockIdx.x;
    int lane = threadIdx.x;   // 32
    float acc[4] = {0.f, 0.f, 0.f, 0.f};
    for (int k = lane; k < 256; k += 32) {
        float v = h2[(size_t)b * 256 + k];
#pragma unroll
        for (int j = 0; j < 4; j++) acc[j] += v * w3[k * 4 + j];
    }
#pragma unroll
    for (int off = 16; off; off >>= 1)
#pragma unroll
        for (int j = 0; j < 4; j++)
            acc[j] += __shfl_down_sync(0xffffffffu, acc[j], off);
    if (lane == 0) {
        float l[4];
#pragma unroll
        for (int j = 0; j < 4; j++) l[j] = acc[j] + b3[j];
        float m = fmaxf(fmaxf(l[0], l[1]), fmaxf(l[2], l[3]));
        float e[4], s = 0.f;
#pragma unroll
        for (int j = 0; j < 4; j++) { e[j] = expf(l[j] - m); s += e[j]; }
        float inv = 1.f / s;
#pragma unroll
        for (int j = 0; j < 4; j++) out[b * 4 + j] = e[j] * inv;
    }
}

// ---------------- host ----------------
template<typename T>
static T* sym(const void* s) {
    void* p = nullptr;
    cudaGetSymbolAddress(&p, s);
    return (T*)p;
}

extern "C" void kernel_launch(void* const* d_in, const int* in_sizes, int n_in,
                              void* d_out, int out_size) {
    const float* x        = (const float*)d_in[0];
    const float* tfe_w    = (const float*)d_in[1];
    const float* tfe_b    = (const float*)d_in[2];
    const float* cheby1_w = (const float*)d_in[3];
    const float* A        = (const float*)d_in[4];
    const float* cheby2_w = (const float*)d_in[5];
    const float* A1       = (const float*)d_in[6];
    const float* b_gate   = (const float*)d_in[7];
    const float* c_gate   = (const float*)d_in[8];

    const float *rw[10], *region_b, *hc_w1, *bn1_g, *bn1_b;
    const float *hc_w2, *bn2_g, *bn2_b, *hc_w3, *hc_b3;

    if (in_sizes[9] == 2560) {
        region_b = (const float*)d_in[9];
        hc_w1    = (const float*)d_in[10];
        bn1_g    = (const float*)d_in[12];
        bn1_b    = (const float*)d_in[13];
        hc_w2    = (const float*)d_in[14];
        bn2_g    = (const float*)d_in[16];
        bn2_b    = (const float*)d_in[17];
        hc_w3    = (const float*)d_in[18];
        hc_b3    = (const float*)d_in[19];
        for (int i = 0; i < 10; i++) rw[i] = (const float*)d_in[20 + i];
    } else {
        for (int i = 0; i < 10; i++) rw[i] = (const float*)d_in[9 + i];
        region_b = (const float*)d_in[19];
        hc_w1    = (const float*)d_in[20];
        bn1_g    = (const float*)d_in[22];
        bn1_b    = (const float*)d_in[23];
        hc_w2    = (const float*)d_in[24];
        bn2_g    = (const float*)d_in[26];
        bn2_b    = (const float*)d_in[27];
        hc_w3    = (const float*)d_in[28];
        hc_b3    = (const float*)d_in[29];
    }

    bf16*  p_gcat   = sym<bf16>(d_gcat);
    bf16*  p_g1     = sym<bf16>(d_g1);
    bf16*  p_regbuf = sym<bf16>(d_regbuf);
    float* p_wTf    = sym<float>(d_wTf);
    bf16*  p_wrT    = sym<bf16>(d_wrT);
    bf16*  p_c1T    = sym<bf16>(d_c1T);
    bf16*  p_c2T    = sym<bf16>(d_c2T);
    bf16*  p_w1T    = sym<bf16>(d_w1T);
    bf16*  p_w2T    = sym<bf16>(d_w2T);
    bf16*  p_g2cat  = sym<bf16>(d_g2cat);
    bf16*  p_g2     = sym<bf16>(d_g2);
    bf16*  p_outb   = sym<bf16>(d_outb);
    float* p_part   = sym<float>(d_part);
    float* p_h1     = sym<float>(d_h1);
    bf16*  p_h1b    = sym<bf16>(d_h1b);
    float* p_h2     = sym<float>(d_h2);
    float* p_A2     = sym<float>(d_A2);
    float* p_A1s    = sym<float>(d_A1s);
    float* p_mean1  = sym<float>(d_mean1);
    float* p_rstd1  = sym<float>(d_rstd1);
    float* p_mean2  = sym<float>(d_mean2);
    float* p_rstd2  = sym<float>(d_rstd2);

    static bool attr_done = false;
    if (!attr_done) {
        cudaFuncSetAttribute(softgate_k, cudaFuncAttributeMaxDynamicSharedMemorySize,
                             72 * 512 * 4);
        attr_done = true;
    }

    // prep: small matrices + weight transpose/convert (all bf16 [N][K])
    a2_k<<<16, 256>>>(A, p_A2);
    a1sq_k<<<1, 128>>>(A1, p_A1s);
    RWPtrs rwp;
    for (int i = 0; i < 10; i++) rwp.p[i] = rw[i];
    wt_k<<<KTOT, 256>>>(rwp, p_wTf);
    cvtT_k<<<dim3(256/32, KTOT/32), dim3(32, 8)>>>(p_wTf, p_wrT, KTOT, 256);
    cvtT_k<<<dim3(512/32, 384/32), dim3(32, 8)>>>(cheby1_w, p_c1T, 384, 512);
    cvtT_k<<<dim3(512/32, 768/32), dim3(32, 8)>>>(cheby2_w, p_c2T, 768, 512);
    cvtT_k<<<dim3(512/32, 36864/32), dim3(32, 8)>>>(hc_w1, p_w1T, 36864, 512);
    cvtT_k<<<dim3(256/32, 512/32), dim3(32, 8)>>>(hc_w2, p_w2T, 512, 256);

    // front-end fuse
    tfe_k<<<BB * XDIM, 128>>>(x, tfe_w, tfe_b, p_gcat);
    applyA_k<<<BB, dim3(128, 4)>>>(A, p_A2, p_gcat);

    // cheby1: (63488 x 384) @ (384 x 512) + relu
    bf16gemm_k<true, false, false, false, true><<<dim3(4, 496), 256>>>(
        p_gcat, p_c1T, p_g1, nullptr, 63488, 512, 384, 384, 384, 512);

    // regions: batched 10 GEMMs (1024 x 256, K = L_i*128) + bias
    gather_k<<<BB * (KTOT/2) / 256, 256>>>(p_gcat, p_regbuf);
    bf16gemm_k<false, true, false, true, true><<<dim3(2, 8, 10), 256>>>(
        p_regbuf, p_wrT, p_g2cat, region_b, 1024, 256, 0, KTOT, KTOT, 7680);

    // cheby2
    applyA1_k<<<BB, 256>>>(A1, p_A1s, p_g2cat);
    bf16gemm_k<true, false, false, false, true><<<dim3(4, 80), 256>>>(
        p_g2cat, p_c2T, p_g2, nullptr, 10240, 512, 768, 768, 768, 512);

    // softmax gate -> (B, 36864) bf16
    softgate_k<<<BB, 512, 72 * 512 * 4>>>(p_g1, p_g2, b_gate, c_gate, p_outb);

    // hc_w1: (1024 x 36864) @ (36864 x 512), split-K=16 (hc_b1 cancels in BN)
    bf16gemm_k<false, false, true, false, false><<<dim3(4, 8, SPLITZ), 256>>>(
        p_outb, p_w1T, p_part, nullptr, 1024, 512, 36864 / SPLITZ, 36864, 36864, 512);
    reduce_part_k<<<2048, 256>>>(p_part, p_h1);

    bnstats_k<<<512, 256>>>(p_h1, 512, p_mean1, p_rstd1);
    bngelu_k<<<2048, 256>>>(p_h1, 512, p_mean1, p_rstd1, bn1_g, bn1_b, p_h1b);

    // hc_w2 (hc_b2 cancels in BN)
    bf16gemm_k<false, false, false, false, false><<<dim3(2, 8), 256>>>(
        p_h1b, p_w2T, p_h2, nullptr, 1024, 256, 512, 512, 512, 256);
    bnstats_k<<<256, 256>>>(p_h2, 256, p_mean2, p_rstd2);
    bngelu_k<<<1024, 256>>>(p_h2, 256, p_mean2, p_rstd2, bn2_g, bn2_b, nullptr);

    // final linear + softmax
    final_k<<<BB, 32>>>(p_h2, hc_w3, hc_b3, (float*)d_out);
}

// round 7
// speedup vs baseline: 5.3973x; 1.0812x over previous
#include <cuda_runtime.h>
#include <cuda_bf16.h>
#include <cstdint>
#include <cstddef>

// ---------------- constants ----------------
#define BB 1024
#define XDIM 62
#define TWIN 10
#define INCH 128
#define MIDD 256
#define OUTD 512
#define KTOT 7936          // 62*128
#define SPLITZ 16

typedef __nv_bfloat16 bf16;

// GEMM smem: 3 stages x (128x40) for A and B
#define GSTG 3
#define GROW 40
#define GEMM_SMEM (GSTG * 128 * GROW * 2 * (int)sizeof(bf16))

// region permutation (concatenation of REGIONS index lists; partitions 0..61)
__constant__ int c_perm[62] = {
    0,1,2,3,4,
    5,6,7,14,15,16,
    8,9,10,17,18,19,
    11,12,13,20,21,22,
    23,24,25,32,33,34,
    26,27,28,35,36,37,
    29,30,31,38,39,40,
    41,42,43,50,51,57,
    44,45,46,52,53,54,58,59,60,
    47,48,49,55,56,61};
__constant__ int c_koff[10] = {0,640,1408,2176,2944,3712,4480,5248,6016,7168};
__constant__ int c_L[10]    = {5,6,6,6,6,6,6,6,9,6};

// ---------------- scratch (device globals; no allocation allowed) ----------------
__device__ bf16  d_gcat[BB*XDIM*384];      // [g | Ag | A2g]  bf16 [M][K]
__device__ bf16  d_g1[BB*XDIM*512];        // cheby1 out bf16
__device__ bf16  d_regbuf[BB*KTOT];
__device__ float d_wTf[KTOT*256];          // fp32 [k][m] staging
__device__ bf16  d_wrT[256*KTOT];          // bf16 [m][k]
__device__ bf16  d_c1T[512*384];           // cheby1_w^T bf16 [N][K]
__device__ bf16  d_c2T[512*768];
__device__ bf16  d_w1T[512*36864];
__device__ bf16  d_w2T[256*512];
__device__ bf16  d_g2cat[BB*10*768];       // [g2in | A1 g2in | A1^2 g2in] bf16
__device__ bf16  d_g2[BB*10*512];
__device__ bf16  d_outb[BB*72*512];
__device__ float d_part[SPLITZ*BB*512];
__device__ float d_h1[BB*512];
__device__ bf16  d_h1b[BB*512];
__device__ float d_h2[BB*256];
__device__ float d_A2[62*62];
__device__ float d_A1s[100];
__device__ float d_mean1[512], d_rstd1[512];
__device__ float d_mean2[256], d_rstd2[256];

// ---------------- ptx helpers ----------------
__device__ __forceinline__ uint32_t smem_u32(const void* p) {
    return (uint32_t)__cvta_generic_to_shared(p);
}
__device__ __forceinline__ void cpasync16(uint32_t s, const void* g) {
    asm volatile("cp.async.cg.shared.global [%0], [%1], 16;" :: "r"(s), "l"(g));
}
__device__ __forceinline__ void cp_commit() {
    asm volatile("cp.async.commit_group;");
}
__device__ __forceinline__ void cp_wait1() {
    asm volatile("cp.async.wait_group 1;");
}

__device__ __forceinline__ void mma16(float* d, const uint32_t* a, uint32_t b0, uint32_t b1) {
    asm volatile(
        "mma.sync.aligned.m16n8k16.row.col.f32.bf16.bf16.f32 "
        "{%0,%1,%2,%3},{%4,%5,%6,%7},{%8,%9},{%0,%1,%2,%3};\n"
        : "+f"(d[0]), "+f"(d[1]), "+f"(d[2]), "+f"(d[3])
        : "r"(a[0]), "r"(a[1]), "r"(a[2]), "r"(a[3]), "r"(b0), "r"(b1));
}

__device__ __forceinline__ void ldsm4(uint32_t& r0, uint32_t& r1, uint32_t& r2, uint32_t& r3,
                                      uint32_t addr) {
    asm volatile("ldmatrix.sync.aligned.m8n8.x4.shared.b16 {%0,%1,%2,%3}, [%4];"
                 : "=r"(r0), "=r"(r1), "=r"(r2), "=r"(r3) : "r"(addr));
}

// ---------------- bf16 tensor-core GEMM (3-stage cp.async + ldmatrix) ----------------
// A: bf16 [M][lda] row-major.  B: bf16 [N][ldb] (weights transposed, K contiguous).
// CTA tile 128x128, K-step 32, 256 threads = 8 warps (4M x 2N), warp tile 32x64.
// grid: x = col tiles, y = row tiles, z = split-K chunk or region index.
// Requires M%128==0, N%128==0, K%32==0.
template<bool RELU, bool BIAS, bool SPLITK, bool REGION, bool OUTBF>
__global__ __launch_bounds__(256, 2)
void bf16gemm_k(const bf16* __restrict__ A, const bf16* __restrict__ Bt,
                void* __restrict__ Cv, const float* __restrict__ bias,
                int M, int N, int K, int lda, int ldb, int ldc) {
    extern __shared__ bf16 smp[];
    bf16 (*As)[128][GROW] = (bf16(*)[128][GROW])smp;
    bf16 (*Bs)[128][GROW] = (bf16(*)[128][GROW])(smp + GSTG * 128 * GROW);

    int tid = threadIdx.x;

    bf16*  Cb = (bf16*)Cv;
    float* Cf = (float*)Cv;

    if (REGION) {
        int rz = blockIdx.z;
        A    += c_koff[rz];
        Bt   += c_koff[rz];
        Cb   += rz * 768;
        if (BIAS) bias += rz * MIDD;
        K = c_L[rz] * 128;
    }
    if (SPLITK) {
        A  += (size_t)blockIdx.z * K;
        Bt += (size_t)blockIdx.z * K;
        Cf += (size_t)blockIdx.z * (size_t)M * N;
    }

    int row0 = blockIdx.y * 128, col0 = blockIdx.x * 128;

    // gmem staging: each thread copies 2x16B of A and of B per stage
    int sr = tid >> 1, ks = (tid & 1) * 16;
    const bf16* Ap = A + (size_t)(row0 + sr) * lda + ks;
    const bf16* Bp = Bt + (size_t)(col0 + sr) * ldb + ks;

    int lane = tid & 31, wid = tid >> 5;
    int wm = wid >> 1, wn = wid & 1;
    int g = lane >> 2, t2 = (lane & 3) * 2;

    // ldmatrix lane addressing
    int mi = lane >> 3, rowin = lane & 7;
    int a_row = wm * 32 + (mi & 1) * 8 + rowin;   // + mm*16
    int a_koff = (mi >> 1) * 8;                   // + kt
    int b_row = wn * 64 + (mi >> 1) * 8 + rowin;  // + pair*16
    int b_koff = (mi & 1) * 8;                    // + kt

    float acc[2][8][4] = {};
    int nk = K >> 5;

    // prologue: stages 0,1
    {
        uint32_t a_s = smem_u32(&As[0][sr][ks]);
        cpasync16(a_s, Ap);
        cpasync16(a_s + 16, Ap + 8);
        uint32_t b_s = smem_u32(&Bs[0][sr][ks]);
        cpasync16(b_s, Bp);
        cpasync16(b_s + 16, Bp + 8);
        cp_commit();
        if (nk > 1) {
            a_s = smem_u32(&As[1][sr][ks]);
            cpasync16(a_s, Ap + 32);
            cpasync16(a_s + 16, Ap + 40);
            b_s = smem_u32(&Bs[1][sr][ks]);
            cpasync16(b_s, Bp + 32);
            cpasync16(b_s + 16, Bp + 40);
        }
        cp_commit();
    }

    int cur = 0;
    for (int k = 0; k < nk; k++) {
        cp_wait1();            // stage k complete (stage k+1 may be pending)
        __syncthreads();

#pragma unroll
        for (int kt = 0; kt < 32; kt += 16) {
            uint32_t a[2][4];
#pragma unroll
            for (int mm = 0; mm < 2; mm++)
                ldsm4(a[mm][0], a[mm][1], a[mm][2], a[mm][3],
                      smem_u32(&As[cur][a_row + mm * 16][a_koff + kt]));
            uint32_t bfr[8][2];
#pragma unroll
            for (int p = 0; p < 4; p++)
                ldsm4(bfr[2 * p][0], bfr[2 * p][1], bfr[2 * p + 1][0], bfr[2 * p + 1][1],
                      smem_u32(&Bs[cur][b_row + p * 16][b_koff + kt]));
#pragma unroll
            for (int nn = 0; nn < 8; nn++) {
                mma16(acc[0][nn], a[0], bfr[nn][0], bfr[nn][1]);
                mma16(acc[1][nn], a[1], bfr[nn][0], bfr[nn][1]);
            }
        }
        __syncthreads();       // done reading buf[cur] before it is refilled

        if (k + 2 < nk) {
            int buf = (k + 2) % GSTG;
            int ko = (k + 2) << 5;
            uint32_t a_s = smem_u32(&As[buf][sr][ks]);
            cpasync16(a_s, Ap + ko);
            cpasync16(a_s + 16, Ap + ko + 8);
            uint32_t b_s = smem_u32(&Bs[buf][sr][ks]);
            cpasync16(b_s, Bp + ko);
            cpasync16(b_s + 16, Bp + ko + 8);
        }
        cp_commit();
        cur = (cur + 1 == GSTG) ? 0 : cur + 1;
    }

    // epilogue
#pragma unroll
    for (int mm = 0; mm < 2; mm++) {
        int r = row0 + wm * 32 + mm * 16 + g;
#pragma unroll
        for (int nn = 0; nn < 8; nn++) {
            int c = col0 + wn * 64 + nn * 8 + t2;
            float v0 = acc[mm][nn][0], v1 = acc[mm][nn][1];
            float v2 = acc[mm][nn][2], v3 = acc[mm][nn][3];
            if (BIAS) {
                float q0 = bias[c], q1 = bias[c + 1];
                v0 += q0; v1 += q1; v2 += q0; v3 += q1;
            }
            if (RELU) {
                v0 = fmaxf(v0, 0.f); v1 = fmaxf(v1, 0.f);
                v2 = fmaxf(v2, 0.f); v3 = fmaxf(v3, 0.f);
            }
            if (OUTBF) {
                __nv_bfloat162* p0 = (__nv_bfloat162*)&Cb[(size_t)r * ldc + c];
                __nv_bfloat162* p1 = (__nv_bfloat162*)&Cb[(size_t)(r + 8) * ldc + c];
                *p0 = __floats2bfloat162_rn(v0, v1);
                *p1 = __floats2bfloat162_rn(v2, v3);
            } else {
                *(float2*)&Cf[(size_t)r * ldc + c] = make_float2(v0, v1);
                *(float2*)&Cf[(size_t)(r + 8) * ldc + c] = make_float2(v2, v3);
            }
        }
    }
}

// ---------------- transpose + convert: fp32 [R][C] -> bf16 [C][R] ----------------
__global__ void cvtT_k(const float* __restrict__ src, bf16* __restrict__ dst,
                       int R, int C) {
    __shared__ float tile[32][33];
    int rb = blockIdx.y * 32, cb = blockIdx.x * 32;
#pragma unroll
    for (int i = 0; i < 32; i += 8)
        tile[threadIdx.y + i][threadIdx.x] =
            src[(size_t)(rb + threadIdx.y + i) * C + cb + threadIdx.x];
    __syncthreads();
#pragma unroll
    for (int i = 0; i < 32; i += 8)
        dst[(size_t)(cb + threadIdx.y + i) * R + rb + threadIdx.x] =
            __float2bfloat16(tile[threadIdx.x][threadIdx.y + i]);
}

// ---------------- small prep kernels ----------------
__global__ void a2_k(const float* __restrict__ A, float* __restrict__ A2) {
    int i = blockIdx.x * blockDim.x + threadIdx.x;
    if (i >= 62*62) return;
    int r = i / 62, c = i % 62;
    float s = 0.f;
    for (int m = 0; m < 62; m++) s += A[r*62+m] * A[m*62+c];
    A2[i] = s;
}

__global__ void a1sq_k(const float* __restrict__ A1, float* __restrict__ A1s) {
    int i = threadIdx.x;
    if (i >= 100) return;
    int r = i / 10, c = i % 10;
    float s = 0.f;
    for (int m = 0; m < 10; m++) s += A1[r*10+m] * A1[m*10+c];
    A1s[i] = s;
}

struct RWPtrs { const float* p[10]; };

// transpose region weights rw_i[m,c,l] -> wTf[(koff_i + l*128 + c)*256 + m]
__global__ void wt_k(RWPtrs rw, float* __restrict__ wT) {
    int e = blockIdx.x * 256 + threadIdx.x;   // < 7936*256
    int m = e & 255;
    int kidx = e >> 8;
    int i = 0;
#pragma unroll
    for (int q = 1; q < 10; q++) if (kidx >= c_koff[q]) i = q;
    int d = kidx - c_koff[i];
    int l = d >> 7, c = d & 127;
    wT[(size_t)kidx * 256 + m] = rw.p[i][(m * 128 + c) * c_L[i] + l];
}

// fused: variance(ddof=1) over TWIN + tfe einsum + exp gate -> g (slice 0, bf16)
__global__ void tfe_k(const float* __restrict__ x, const float* __restrict__ w,
                      const float* __restrict__ bvec, bf16* __restrict__ gcat) {
    int bc = blockIdx.x;           // b*62 + c
    int c = bc % 62;
    int t = threadIdx.x;           // 0..127
    const float* xp = x + (size_t)bc * TWIN * INCH + t;
    float s1 = 0.f, s2 = 0.f, ws = 0.f;
#pragma unroll
    for (int i = 0; i < TWIN; i++) {
        float v = xp[(size_t)i * INCH];
        s1 += v; s2 += v * v;
        ws += v * w[c * TWIN + i];
    }
    float var = (s2 - s1 * s1 * 0.1f) * (1.f / 9.f);   // ddof=1
    float g = (ws + bvec[c]) * expf(-var);
    gcat[(size_t)bc * 384 + t] = __float2bfloat16(g);
}

// compute Ag, A^2 g into slices 1,2 of gcat (bf16 in/out, fp32 math)
__global__ void applyA_k(const float* __restrict__ A, const float* __restrict__ A2,
                         bf16* __restrict__ gcat) {
    __shared__ float gs[62][128];
    int b = blockIdx.x;
    int t = threadIdx.x;   // 128
    int yy = threadIdx.y;  // 4
    for (int n = yy; n < 62; n += 4)
        gs[n][t] = __bfloat162float(gcat[((size_t)b * 62 + n) * 384 + t]);
    __syncthreads();
#pragma unroll
    for (int base = 0; base < 64; base += 16) {
        int n = base + yy * 4;
        float s1[4] = {0,0,0,0}, s2[4] = {0,0,0,0};
        bool val[4];
#pragma unroll
        for (int q = 0; q < 4; q++) val[q] = (n + q) < 62;
        for (int m = 0; m < 62; m++) {
            float v = gs[m][t];
#pragma unroll
            for (int q = 0; q < 4; q++) {
                if (val[q]) {
                    s1[q] += A[(n + q) * 62 + m] * v;
                    s2[q] += A2[(n + q) * 62 + m] * v;
                }
            }
        }
#pragma unroll
        for (int q = 0; q < 4; q++) {
            if (val[q]) {
                gcat[((size_t)b * 62 + n + q) * 384 + 128 + t] = __float2bfloat16(s1[q]);
                gcat[((size_t)b * 62 + n + q) * 384 + 256 + t] = __float2bfloat16(s2[q]);
            }
        }
    }
}

// gather permuted region rows (u32 = 2 bf16 at a time)
__global__ void gather_k(const bf16* __restrict__ gcat, bf16* __restrict__ regbuf) {
    size_t e = (size_t)blockIdx.x * 256 + threadIdx.x;   // < 1024*3968
    int b = (int)(e / (KTOT / 2));
    int j = (int)(e % (KTOT / 2));                       // u32 index in row
    int l = j >> 6, cp = j & 63;
    const uint32_t* src = (const uint32_t*)&gcat[((size_t)b * 62 + c_perm[l]) * 384 + cp * 2];
    ((uint32_t*)regbuf)[e] = *src;
}

// A1, A1^2 apply for cheby2 (slices 1,2 of g2cat, bf16)
__global__ void applyA1_k(const float* __restrict__ A1, const float* __restrict__ A1s,
                          bf16* __restrict__ g2cat) {
    int b = blockIdx.x;
    int t = threadIdx.x;   // 256
    float v[10];
#pragma unroll
    for (int m = 0; m < 10; m++)
        v[m] = __bfloat162float(g2cat[((size_t)b * 10 + m) * 768 + t]);
#pragma unroll
    for (int n = 0; n < 10; n++) {
        float s1 = 0.f, s2 = 0.f;
#pragma unroll
        for (int m = 0; m < 10; m++) {
            s1 += A1[n * 10 + m] * v[m];
            s2 += A1s[n * 10 + m] * v[m];
        }
        g2cat[((size_t)b * 10 + n) * 768 + 256 + t] = __float2bfloat16(s1);
        g2cat[((size_t)b * 10 + n) * 768 + 512 + t] = __float2bfloat16(s2);
    }
}

// ---------------- softmax gate (bf16 in, bf16 out) ----------------
__global__ void softgate_k(const bf16* __restrict__ g1, const bf16* __restrict__ g2,
                           const float* __restrict__ bg, const float* __restrict__ cg,
                           bf16* __restrict__ outb) {
    extern __shared__ float sm[];   // 72 * 512
    int b = blockIdx.x;
    int o = threadIdx.x;   // 512
    float Bg = *bg, Cg = *cg;
#pragma unroll 2
    for (int s = 0; s < 62; s++)
        sm[s * 512 + o] = __bfloat162float(g1[((size_t)b * 62 + s) * 512 + o]);
#pragma unroll
    for (int s = 0; s < 10; s++)
        sm[(62 + s) * 512 + o] = __bfloat162float(g2[((size_t)b * 10 + s) * 512 + o]);
    __syncthreads();
    float M = -1e30f, S = 0.f;
#pragma unroll 2
    for (int s = 0; s < 72; s++) {
        float a = ((s < 62) ? Bg : Cg) * sm[s * 512 + o];
        float nM = fmaxf(M, a);
        S = S * expf(M - nM) + expf(a - nM);
        M = nM;
    }
    float inv = 1.f / S;
#pragma unroll 2
    for (int s = 0; s < 72; s++) {
        float v = sm[s * 512 + o];
        float a = ((s < 62) ? Bg : Cg) * v;
        outb[(size_t)b * 36864 + s * 512 + o] = __float2bfloat16(expf(a - M) * inv * v);
    }
}

// ---------------- split-K reduce ----------------
__global__ void reduce_part_k(const float* __restrict__ part, float* __restrict__ out) {
    int i = blockIdx.x * 256 + threadIdx.x;   // < 1024*512
    float s = 0.f;
#pragma unroll
    for (int z = 0; z < SPLITZ; z++) s += part[(size_t)z * (BB * 512) + i];
    out[i] = s;
}

// ---------------- batch-norm stats + bn*gelu ----------------
__global__ void bnstats_k(const float* __restrict__ h, int F,
                          float* __restrict__ mean, float* __restrict__ rstd) {
    __shared__ float sh1[256], sh2[256];
    int j = blockIdx.x;
    float s1 = 0.f, s2 = 0.f;
    for (int b = threadIdx.x; b < BB; b += 256) {
        float v = h[(size_t)b * F + j];
        s1 += v; s2 += v * v;
    }
    sh1[threadIdx.x] = s1; sh2[threadIdx.x] = s2;
    __syncthreads();
    for (int o = 128; o; o >>= 1) {
        if (threadIdx.x < o) {
            sh1[threadIdx.x] += sh1[threadIdx.x + o];
            sh2[threadIdx.x] += sh2[threadIdx.x + o];
        }
        __syncthreads();
    }
    if (threadIdx.x == 0) {
        float mu = sh1[0] * (1.f / BB);
        float var = sh2[0] * (1.f / BB) - mu * mu;
        mean[j] = mu;
        rstd[j] = rsqrtf(var + 1e-5f);
    }
}

__global__ void bngelu_k(float* __restrict__ h, int F,
                         const float* __restrict__ mean, const float* __restrict__ rstd,
                         const float* __restrict__ gam, const float* __restrict__ bet,
                         bf16* __restrict__ hb) {
    int i = blockIdx.x * 256 + threadIdx.x;
    int j = i % F;
    float v = (h[i] - mean[j]) * rstd[j] * gam[j] + bet[j];
    float r = 0.5f * v * (1.f + erff(v * 0.70710678118654752f));
    h[i] = r;
    if (hb) hb[i] = __float2bfloat16(r);
}

// ---------------- final linear + softmax ----------------
__global__ void final_k(const float* __restrict__ h2, const float* __restrict__ w3,
                        const float* __restrict__ b3, float* __restrict__ out) {
    int b = blockIdx.x;
    int lane = threadIdx.x;   // 32
    float acc[4] = {0.f, 0.f, 0.f, 0.f};
    for (int k = lane; k < 256; k += 32) {
        float v = h2[(size_t)b * 256 + k];
#pragma unroll
        for (int j = 0; j < 4; j++) acc[j] += v * w3[k * 4 + j];
    }
#pragma unroll
    for (int off = 16; off; off >>= 1)
#pragma unroll
        for (int j = 0; j < 4; j++)
            acc[j] += __shfl_down_sync(0xffffffffu, acc[j], off);
    if (lane == 0) {
        float l[4];
#pragma unroll
        for (int j = 0; j < 4; j++) l[j] = acc[j] + b3[j];
        float m = fmaxf(fmaxf(l[0], l[1]), fmaxf(l[2], l[3]));
        float e[4], s = 0.f;
#pragma unroll
        for (int j = 0; j < 4; j++) { e[j] = expf(l[j] - m); s += e[j]; }
        float inv = 1.f / s;
#pragma unroll
        for (int j = 0; j < 4; j++) out[b * 4 + j] = e[j] * inv;
    }
}

// ---------------- host ----------------
template<typename T>
static T* sym(const void* s) {
    void* p = nullptr;
    cudaGetSymbolAddress(&p, s);
    return (T*)p;
}

extern "C" void kernel_launch(void* const* d_in, const int* in_sizes, int n_in,
                              void* d_out, int out_size) {
    const float* x        = (const float*)d_in[0];
    const float* tfe_w    = (const float*)d_in[1];
    const float* tfe_b    = (const float*)d_in[2];
    const float* cheby1_w = (const float*)d_in[3];
    const float* A        = (const float*)d_in[4];
    const float* cheby2_w = (const float*)d_in[5];
    const float* A1       = (const float*)d_in[6];
    const float* b_gate   = (const float*)d_in[7];
    const float* c_gate   = (const float*)d_in[8];

    const float *rw[10], *region_b, *hc_w1, *bn1_g, *bn1_b;
    const float *hc_w2, *bn2_g, *bn2_b, *hc_w3, *hc_b3;

    if (in_sizes[9] == 2560) {
        region_b = (const float*)d_in[9];
        hc_w1    = (const float*)d_in[10];
        bn1_g    = (const float*)d_in[12];
        bn1_b    = (const float*)d_in[13];
        hc_w2    = (const float*)d_in[14];
        bn2_g    = (const float*)d_in[16];
        bn2_b    = (const float*)d_in[17];
        hc_w3    = (const float*)d_in[18];
        hc_b3    = (const float*)d_in[19];
        for (int i = 0; i < 10; i++) rw[i] = (const float*)d_in[20 + i];
    } else {
        for (int i = 0; i < 10; i++) rw[i] = (const float*)d_in[9 + i];
        region_b = (const float*)d_in[19];
        hc_w1    = (const float*)d_in[20];
        bn1_g    = (const float*)d_in[22];
        bn1_b    = (const float*)d_in[23];
        hc_w2    = (const float*)d_in[24];
        bn2_g    = (const float*)d_in[26];
        bn2_b    = (const float*)d_in[27];
        hc_w3    = (const float*)d_in[28];
        hc_b3    = (const float*)d_in[29];
    }

    bf16*  p_gcat   = sym<bf16>(d_gcat);
    bf16*  p_g1     = sym<bf16>(d_g1);
    bf16*  p_regbuf = sym<bf16>(d_regbuf);
    float* p_wTf    = sym<float>(d_wTf);
    bf16*  p_wrT    = sym<bf16>(d_wrT);
    bf16*  p_c1T    = sym<bf16>(d_c1T);
    bf16*  p_c2T    = sym<bf16>(d_c2T);
    bf16*  p_w1T    = sym<bf16>(d_w1T);
    bf16*  p_w2T    = sym<bf16>(d_w2T);
    bf16*  p_g2cat  = sym<bf16>(d_g2cat);
    bf16*  p_g2     = sym<bf16>(d_g2);
    bf16*  p_outb   = sym<bf16>(d_outb);
    float* p_part   = sym<float>(d_part);
    float* p_h1     = sym<float>(d_h1);
    bf16*  p_h1b    = sym<bf16>(d_h1b);
    float* p_h2     = sym<float>(d_h2);
    float* p_A2     = sym<float>(d_A2);
    float* p_A1s    = sym<float>(d_A1s);
    float* p_mean1  = sym<float>(d_mean1);
    float* p_rstd1  = sym<float>(d_rstd1);
    float* p_mean2  = sym<float>(d_mean2);
    float* p_rstd2  = sym<float>(d_rstd2);

    static bool attr_done = false;
    if (!attr_done) {
        cudaFuncSetAttribute(softgate_k, cudaFuncAttributeMaxDynamicSharedMemorySize,
                             72 * 512 * 4);
        cudaFuncSetAttribute(bf16gemm_k<true, false, false, false, true>,
                             cudaFuncAttributeMaxDynamicSharedMemorySize, GEMM_SMEM);
        cudaFuncSetAttribute(bf16gemm_k<false, true, false, true, true>,
                             cudaFuncAttributeMaxDynamicSharedMemorySize, GEMM_SMEM);
        cudaFuncSetAttribute(bf16gemm_k<false, false, true, false, false>,
                             cudaFuncAttributeMaxDynamicSharedMemorySize, GEMM_SMEM);
        cudaFuncSetAttribute(bf16gemm_k<false, false, false, false, false>,
                             cudaFuncAttributeMaxDynamicSharedMemorySize, GEMM_SMEM);
        attr_done = true;
    }

    // prep: small matrices + weight transpose/convert (all bf16 [N][K])
    a2_k<<<16, 256>>>(A, p_A2);
    a1sq_k<<<1, 128>>>(A1, p_A1s);
    RWPtrs rwp;
    for (int i = 0; i < 10; i++) rwp.p[i] = rw[i];
    wt_k<<<KTOT, 256>>>(rwp, p_wTf);
    cvtT_k<<<dim3(256/32, KTOT/32), dim3(32, 8)>>>(p_wTf, p_wrT, KTOT, 256);
    cvtT_k<<<dim3(512/32, 384/32), dim3(32, 8)>>>(cheby1_w, p_c1T, 384, 512);
    cvtT_k<<<dim3(512/32, 768/32), dim3(32, 8)>>>(cheby2_w, p_c2T, 768, 512);
    cvtT_k<<<dim3(512/32, 36864/32), dim3(32, 8)>>>(hc_w1, p_w1T, 36864, 512);
    cvtT_k<<<dim3(256/32, 512/32), dim3(32, 8)>>>(hc_w2, p_w2T, 512, 256);

    // front-end fuse
    tfe_k<<<BB * XDIM, 128>>>(x, tfe_w, tfe_b, p_gcat);
    applyA_k<<<BB, dim3(128, 4)>>>(A, p_A2, p_gcat);

    // cheby1: (63488 x 384) @ (384 x 512) + relu
    bf16gemm_k<true, false, false, false, true><<<dim3(4, 496), 256, GEMM_SMEM>>>(
        p_gcat, p_c1T, p_g1, nullptr, 63488, 512, 384, 384, 384, 512);

    // regions: batched 10 GEMMs (1024 x 256, K = L_i*128) + bias
    gather_k<<<BB * (KTOT/2) / 256, 256>>>(p_gcat, p_regbuf);
    bf16gemm_k<false, true, false, true, true><<<dim3(2, 8, 10), 256, GEMM_SMEM>>>(
        p_regbuf, p_wrT, p_g2cat, region_b, 1024, 256, 0, KTOT, KTOT, 7680);

    // cheby2
    applyA1_k<<<BB, 256>>>(A1, p_A1s, p_g2cat);
    bf16gemm_k<true, false, false, false, true><<<dim3(4, 80), 256, GEMM_SMEM>>>(
        p_g2cat, p_c2T, p_g2, nullptr, 10240, 512, 768, 768, 768, 512);

    // softmax gate -> (B, 36864) bf16
    softgate_k<<<BB, 512, 72 * 512 * 4>>>(p_g1, p_g2, b_gate, c_gate, p_outb);

    // hc_w1: (1024 x 36864) @ (36864 x 512), split-K=16 (hc_b1 cancels in BN)
    bf16gemm_k<false, false, true, false, false><<<dim3(4, 8, SPLITZ), 256, GEMM_SMEM>>>(
        p_outb, p_w1T, p_part, nullptr, 1024, 512, 36864 / SPLITZ, 36864, 36864, 512);
    reduce_part_k<<<2048, 256>>>(p_part, p_h1);

    bnstats_k<<<512, 256>>>(p_h1, 512, p_mean1, p_rstd1);
    bngelu_k<<<2048, 256>>>(p_h1, 512, p_mean1, p_rstd1, bn1_g, bn1_b, p_h1b);

    // hc_w2 (hc_b2 cancels in BN)
    bf16gemm_k<false, false, false, false, false><<<dim3(2, 8), 256, GEMM_SMEM>>>(
        p_h1b, p_w2T, p_h2, nullptr, 1024, 256, 512, 512, 512, 256);
    bnstats_k<<<256, 256>>>(p_h2, 256, p_mean2, p_rstd2);
    bngelu_k<<<1024, 256>>>(p_h2, 256, p_mean2, p_rstd2, bn2_g, bn2_b, nullptr);

    // final linear + softmax
    final_k<<<BB, 32>>>(p_h2, hc_w3, hc_b3, (float*)d_out);
}